// round 1
// baseline (speedup 1.0000x reference)
#include <cuda_runtime.h>
#include <math.h>

#define NHEADS 16
#define DHEAD  64
#define DMODEL 1024
#define BATCH  2
#define QSCALE 0.125f
#define MAXTOK 1024
#define NU1 2047
#define NU2 1023
#define NU3 511
#define LNEPS 1e-9f

// ---------------- device scratch (static: no allocations allowed) ----------------
__device__ float g_q  [BATCH*MAXTOK*DMODEL];
__device__ float g_k  [BATCH*MAXTOK*DMODEL];
__device__ float g_v  [BATCH*MAXTOK*DMODEL];
__device__ float g_qw [BATCH*MAXTOK*DMODEL];
__device__ float g_qq [BATCH*MAXTOK*DMODEL];
__device__ float g_vec[BATCH*MAXTOK*DMODEL];
__device__ float g_tmp[BATCH*MAXTOK*DMODEL];
__device__ float g_hA [BATCH*MAXTOK*DMODEL];
__device__ float g_hB [BATCH*MAXTOK*DMODEL];
__device__ float g_up [BATCH*MAXTOK*DMODEL];
__device__ float g_S  [(size_t)BATCH*NHEADS*MAXTOK*MAXTOK];   // scores / probs
__device__ float g_P  [(size_t)BATCH*NHEADS*MAXTOK*NU1];      // rel-pos projections
__device__ float g_REL[NHEADS*DHEAD*NU1];
__device__ float g_rkT[NHEADS*DHEAD*DMODEL];
__device__ float g_R1 [NU1*DMODEL];
__device__ float g_R2 [NU2*DMODEL];
__device__ float g_R3 [NU3*DMODEL];
__device__ float g_tt0[BATCH*NHEADS*MAXTOK];
__device__ float g_dtt[BATCH*NHEADS*MAXTOK];

// ---------------- reductions ----------------
__device__ __forceinline__ float blockReduceSum(float v, float* red) {
    __syncthreads();
    #pragma unroll
    for (int o = 16; o > 0; o >>= 1) v += __shfl_down_sync(0xffffffffu, v, o);
    int lane = threadIdx.x & 31, w = threadIdx.x >> 5;
    if (lane == 0) red[w] = v;
    __syncthreads();
    int nw = (blockDim.x + 31) >> 5;
    if (w == 0) {
        v = (lane < nw) ? red[lane] : 0.f;
        #pragma unroll
        for (int o = 16; o > 0; o >>= 1) v += __shfl_down_sync(0xffffffffu, v, o);
        if (lane == 0) red[0] = v;
    }
    __syncthreads();
    return red[0];
}

__device__ __forceinline__ float blockReduceMax(float v, float* red) {
    __syncthreads();
    #pragma unroll
    for (int o = 16; o > 0; o >>= 1) v = fmaxf(v, __shfl_down_sync(0xffffffffu, v, o));
    int lane = threadIdx.x & 31, w = threadIdx.x >> 5;
    if (lane == 0) red[w] = v;
    __syncthreads();
    int nw = (blockDim.x + 31) >> 5;
    if (w == 0) {
        v = (lane < nw) ? red[lane] : -1e30f;
        #pragma unroll
        for (int o = 16; o > 0; o >>= 1) v = fmaxf(v, __shfl_down_sync(0xffffffffu, v, o));
        if (lane == 0) red[0] = v;
    }
    __syncthreads();
    return red[0];
}

// ---------------- general batched strided GEMM ----------------
// C = alpha * A @ op(B) (+ biasAlpha*bias[col]) (+= C if accum)
// batch bz = bo*innerCount + bi ; per-matrix base offset = bo*xO + bi*xI
__global__ void gemm_k(const float* __restrict__ A, const float* __restrict__ Bm,
                       const float* __restrict__ bias, float* __restrict__ C,
                       int M, int N, int K, int lda, int ldb, int ldc,
                       long aO, long aI, long bO, long bI, long cO, long cI,
                       int innerCount, int transB, int accum,
                       float alpha, float biasAlpha)
{
    int bz = blockIdx.z;
    int bo = bz / innerCount, bi = bz % innerCount;
    A  += bo * aO + bi * aI;
    Bm += bo * bO + bi * bI;
    C  += bo * cO + bi * cI;

    __shared__ float As[16][65];
    __shared__ float Bs[16][65];

    int tid = threadIdx.x;
    int tm = (tid >> 4) << 2;
    int tn = (tid & 15) << 2;
    int rowBase = blockIdx.y * 64;
    int colBase = blockIdx.x * 64;

    float acc[4][4];
    #pragma unroll
    for (int x = 0; x < 4; x++)
        #pragma unroll
        for (int y = 0; y < 4; y++) acc[x][y] = 0.f;

    for (int k0 = 0; k0 < K; k0 += 16) {
        for (int t = tid; t < 64 * 16; t += 256) {
            int m = t >> 4, kk = t & 15;
            int gm = rowBase + m, gk = k0 + kk;
            As[kk][m] = (gm < M && gk < K) ? A[(long)gm * lda + gk] : 0.f;
        }
        for (int t = tid; t < 16 * 64; t += 256) {
            int kk = t >> 6, n = t & 63;
            int gk = k0 + kk, gn = colBase + n;
            float v = 0.f;
            if (gk < K && gn < N)
                v = transB ? Bm[(long)gn * ldb + gk] : Bm[(long)gk * ldb + gn];
            Bs[kk][n] = v;
        }
        __syncthreads();
        #pragma unroll
        for (int kk = 0; kk < 16; kk++) {
            float a[4], b[4];
            #pragma unroll
            for (int x = 0; x < 4; x++) { a[x] = As[kk][tm + x]; b[x] = Bs[kk][tn + x]; }
            #pragma unroll
            for (int x = 0; x < 4; x++)
                #pragma unroll
                for (int y = 0; y < 4; y++) acc[x][y] += a[x] * b[y];
        }
        __syncthreads();
    }

    #pragma unroll
    for (int x = 0; x < 4; x++) {
        int gm = rowBase + tm + x;
        if (gm >= M) continue;
        #pragma unroll
        for (int y = 0; y < 4; y++) {
            int gn = colBase + tn + y;
            if (gn >= N) continue;
            float v = alpha * acc[x][y];
            if (bias) v += biasAlpha * bias[gn];
            long off = (long)gm * ldc + gn;
            if (accum) v += C[off];
            C[off] = v;
        }
    }
}

// ---------------- relative-position basis: rel(pos,d) ----------------
// R[u*DMODEL + d] : d<512 -> sin((g*u+d0)*invf_d) ; d>=512 -> cos(... invf_{d-512})
__global__ void relmat_k(float* __restrict__ R, int nU, int g, int d0)
{
    long idx = (long)blockIdx.x * blockDim.x + threadIdx.x;
    long tot = (long)nU * DMODEL;
    if (idx >= tot) return;
    int u = (int)(idx / DMODEL), d = (int)(idx % DMODEL);
    int f = (d < 512) ? d : d - 512;
    float invf = expf(-(float)f * (9.210340371976184f / 512.0f)); // 10000^(-f/512)
    float arg = (float)(g * u + d0) * invf;
    R[idx] = (d < 512) ? sinf(arg) : cosf(arg);
}

// transpose r_kernel (D, NH, DH) -> (NH*DH, D)
__global__ void rkT_k(const float* __restrict__ rk, float* __restrict__ rkT)
{
    int idx = blockIdx.x * blockDim.x + threadIdx.x;
    if (idx >= DMODEL * NHEADS * DHEAD) return;
    int d = idx / (NHEADS * DHEAD), nh = idx % (NHEADS * DHEAD);
    rkT[(long)nh * DMODEL + d] = rk[idx];
}

// qw = q + SCALE*rw[d], qq = q + SCALE*rr[d]
__global__ void addbias2_k(const float* __restrict__ q, const float* __restrict__ rw,
                           const float* __restrict__ rr, float* __restrict__ qw,
                           float* __restrict__ qq, long total)
{
    long i = (long)blockIdx.x * blockDim.x + threadIdx.x;
    if (i >= total) return;
    int d = (int)(i % DMODEL);
    float v = q[i];
    qw[i] = v + QSCALE * rw[d];
    qq[i] = v + QSCALE * rr[d];
}

// token-type biases: ttb0 and (ttb1-ttb0) per (b,n,i)
__global__ void ttb_k(const float* __restrict__ q, const float* __restrict__ rs,
                      const float* __restrict__ seg, float* __restrict__ tt0,
                      float* __restrict__ dtt, int Lq)
{
    int idx = blockIdx.x * blockDim.x + threadIdx.x;
    if (idx >= BATCH * NHEADS * Lq) return;
    int i = idx % Lq; int bn = idx / Lq; int n = bn % NHEADS; int b = bn / NHEADS;
    const float* qp  = q + ((long)(b * Lq + i)) * DMODEL + n * DHEAD;
    const float* rsp = rs + n * DHEAD;
    const float* s0  = seg + n * DHEAD;           // seg[l][0][n][:]
    const float* s1  = seg + DMODEL + n * DHEAD;  // seg[l][1][n][:]
    float t0 = 0.f, t1 = 0.f;
    #pragma unroll 8
    for (int h = 0; h < DHEAD; h++) {
        float v = qp[h] + QSCALE * rsp[h];
        t0 += v * s0[h];
        t1 += v * s1[h];
    }
    tt0[(long)bn * Lq + i] = t0;
    dtt[(long)bn * Lq + i] = t1 - t0;
}

// assemble scores (content + rel-pos gather + token-type) and softmax in place
__global__ void softmax_k(float* __restrict__ S, const float* __restrict__ P,
                          const float* __restrict__ tt0, const float* __restrict__ dtt,
                          const int* __restrict__ ids,
                          int Lq, int Lk, int nU, int cq, int ck, int u0, int pq, int pk)
{
    int i = blockIdx.x, n = blockIdx.y, b = blockIdx.z;
    int bn = b * NHEADS + n;
    float* Srow = S + ((long)bn * Lq + i) * Lk;
    const float* Prow = P + ((long)bn * Lq + i) * nU;
    float t0 = tt0[(long)bn * Lq + i], dt = dtt[(long)bn * Lq + i];
    const int* idk = ids + b * 1024;
    int idq = idk[pq * i];
    int ubase = cq * i + u0;

    __shared__ float sh[MAXTOK];
    __shared__ float red[32];
    int tid = threadIdx.x;

    float lmax = -1e30f;
    for (int j = tid; j < Lk; j += blockDim.x) {
        float tok = (idk[pk * j] == idq) ? (t0 + dt) : t0;
        float v = Srow[j] + Prow[ubase + ck * j] + tok;
        sh[j] = v;
        lmax = fmaxf(lmax, v);
    }
    float bmax = blockReduceMax(lmax, red);

    float lsum = 0.f;
    for (int j = tid; j < Lk; j += blockDim.x) {
        float e = expf(sh[j] - bmax);
        sh[j] = e;
        lsum += e;
    }
    float bsum = blockReduceSum(lsum, red);
    float inv = 1.0f / bsum;
    for (int j = tid; j < Lk; j += blockDim.x) Srow[j] = sh[j] * inv;
}

// out = LayerNorm(qin + tmp) * g + b
__global__ void ln_k(const float* __restrict__ qin, const float* __restrict__ tmp,
                     const float* __restrict__ gvec, const float* __restrict__ bvec,
                     float* __restrict__ out)
{
    int r = blockIdx.x, tid = threadIdx.x;
    const float* x1 = qin + (long)r * DMODEL;
    const float* x2 = tmp + (long)r * DMODEL;
    __shared__ float red[32];
    float s = 0.f;
    for (int d = tid; d < DMODEL; d += blockDim.x) s += x1[d] + x2[d];
    float mu = blockReduceSum(s, red) * (1.0f / DMODEL);
    float vs = 0.f;
    for (int d = tid; d < DMODEL; d += blockDim.x) {
        float z = x1[d] + x2[d] - mu;
        vs += z * z;
    }
    float var = blockReduceSum(vs, red) * (1.0f / DMODEL);
    float rstd = rsqrtf(var + LNEPS);
    for (int d = tid; d < DMODEL; d += blockDim.x) {
        float z = x1[d] + x2[d] - mu;
        out[(long)r * DMODEL + d] = z * rstd * gvec[d] + bvec[d];
    }
}

// _upsample: out[2t]=h[t], out[2t+1]=0.5*(h[t]+h[t-1 (wrap)])
__global__ void upsample_k(const float* __restrict__ h, float* __restrict__ out, int Lin)
{
    long idx = (long)blockIdx.x * blockDim.x + threadIdx.x;
    long total = (long)BATCH * Lin * DMODEL;
    if (idx >= total) return;
    int d = (int)(idx % DMODEL);
    long bt = idx / DMODEL;
    int t = (int)(bt % Lin);
    int b = (int)(bt / Lin);
    float cur = h[idx];
    int tp = (t == 0) ? Lin - 1 : t - 1;
    float prev = h[((long)b * Lin + tp) * DMODEL + d];
    long ob = ((long)b * (2 * Lin) + 2 * t) * DMODEL + d;
    out[ob] = cur;
    out[ob + DMODEL] = 0.5f * (cur + prev);
}

// ---------------- host ----------------
static void gemm(const float* A, const float* B, const float* bias, float* C,
                 int M, int N, int K, int lda, int ldb, int ldc,
                 long aO, long aI, long bO, long bI, long cO, long cI,
                 int innerCount, int batches, int transB, int accum,
                 float alpha, float biasAlpha)
{
    dim3 grid((N + 63) / 64, (M + 63) / 64, batches);
    gemm_k<<<grid, 256>>>(A, B, bias, C, M, N, K, lda, ldb, ldc,
                          aO, aI, bO, bI, cO, cI, innerCount, transB, accum,
                          alpha, biasAlpha);
}

extern "C" void kernel_launch(void* const* d_in, const int* in_sizes, int n_in,
                              void* d_out, int out_size)
{
    const float* final_hidden = (const float*)d_in[0];
    const int*   tok_ids      = (const int*)d_in[5];
    const float* Wq = (const float*)d_in[6];
    const float* bq = (const float*)d_in[7];
    const float* Wk = (const float*)d_in[8];
    const float* bk = (const float*)d_in[9];
    const float* Wv = (const float*)d_in[10];
    const float* bv = (const float*)d_in[11];
    const float* rw = (const float*)d_in[12];
    const float* rr = (const float*)d_in[13];
    const float* rs = (const float*)d_in[14];
    const float* rk = (const float*)d_in[15];
    const float* sg = (const float*)d_in[16];
    const float* Wp = (const float*)d_in[17];
    const float* bp = (const float*)d_in[18];
    const float* lg = (const float*)d_in[19];
    const float* lb = (const float*)d_in[20];
    float* out = (float*)d_out;

    float *p_q,*p_k,*p_v,*p_qw,*p_qq,*p_vec,*p_tmp,*p_hA,*p_hB,*p_up;
    float *p_S,*p_P,*p_REL,*p_rkT,*p_R1,*p_R2,*p_R3,*p_t0,*p_dt;
    cudaGetSymbolAddress((void**)&p_q,  g_q);
    cudaGetSymbolAddress((void**)&p_k,  g_k);
    cudaGetSymbolAddress((void**)&p_v,  g_v);
    cudaGetSymbolAddress((void**)&p_qw, g_qw);
    cudaGetSymbolAddress((void**)&p_qq, g_qq);
    cudaGetSymbolAddress((void**)&p_vec,g_vec);
    cudaGetSymbolAddress((void**)&p_tmp,g_tmp);
    cudaGetSymbolAddress((void**)&p_hA, g_hA);
    cudaGetSymbolAddress((void**)&p_hB, g_hB);
    cudaGetSymbolAddress((void**)&p_up, g_up);
    cudaGetSymbolAddress((void**)&p_S,  g_S);
    cudaGetSymbolAddress((void**)&p_P,  g_P);
    cudaGetSymbolAddress((void**)&p_REL,g_REL);
    cudaGetSymbolAddress((void**)&p_rkT,g_rkT);
    cudaGetSymbolAddress((void**)&p_R1, g_R1);
    cudaGetSymbolAddress((void**)&p_R2, g_R2);
    cudaGetSymbolAddress((void**)&p_R3, g_R3);
    cudaGetSymbolAddress((void**)&p_t0, g_tt0);
    cudaGetSymbolAddress((void**)&p_dt, g_dtt);

    // rel-pos basis tables (cheap; rebuilt each call, deterministic)
    {
        long t1 = (long)NU1 * DMODEL;
        relmat_k<<<(unsigned)((t1 + 255) / 256), 256>>>(p_R1, NU1, 1, -1023);
        long t2 = (long)NU2 * DMODEL;
        relmat_k<<<(unsigned)((t2 + 255) / 256), 256>>>(p_R2, NU2, 2, -1022);
        long t3 = (long)NU3 * DMODEL;
        relmat_k<<<(unsigned)((t3 + 255) / 256), 256>>>(p_R3, NU3, 4, -1020);
    }

    const float* hidden = final_hidden;
    float* bufs[2] = {p_hA, p_hB};
    int pb = 0;

    for (int l = 11; l >= 0; --l) {
        int Lq, Lk, do_up, nU, cq, ck, u0, pq, pk; float* R;
        if (l <= 3)      { Lq=1024; Lk=1024; do_up=0; nU=NU1; R=p_R1; cq= 1; ck=-1; u0=1023; pq=1; pk=1; }
        else if (l == 4) { Lq=1024; Lk=512;  do_up=1; nU=NU1; R=p_R1; cq=-1; ck= 2; u0=1023; pq=1; pk=2; }
        else if (l <= 7) { Lq=512;  Lk=512;  do_up=0; nU=NU2; R=p_R2; cq= 1; ck=-1; u0=511;  pq=2; pk=2; }
        else if (l == 8) { Lq=512;  Lk=256;  do_up=1; nU=NU2; R=p_R2; cq=-1; ck= 2; u0=511;  pq=2; pk=4; }
        else             { Lq=256;  Lk=256;  do_up=0; nU=NU3; R=p_R3; cq= 1; ck=-1; u0=255;  pq=4; pk=4; }

        // upsample captured at block ENTRY (before the 3 same-length layers run)
        if (l == 11) { long t = (long)BATCH * 256 * DMODEL; upsample_k<<<(unsigned)((t+255)/256), 256>>>(hidden, p_up, 256); }
        if (l == 7)  { long t = (long)BATCH * 512 * DMODEL; upsample_k<<<(unsigned)((t+255)/256), 256>>>(hidden, p_up, 512); }

        const float* q_in = do_up ? p_up : hidden;
        const float* kv = hidden;

        // REL[n,h,u] = sum_d rk[d,n,h] * relbasis[u,d]
        rkT_k<<<(DMODEL*NHEADS*DHEAD + 255)/256, 256>>>(rk + (long)l*DMODEL*NHEADS*DHEAD, p_rkT);
        gemm(p_rkT, R, nullptr, p_REL, DHEAD, nU, DMODEL,
             DMODEL, DMODEL, nU,
             0, (long)DHEAD*DMODEL, 0, 0, 0, (long)DHEAD*nU,
             NHEADS, NHEADS, 1, 0, 1.f, 0.f);

        // projections
        gemm(q_in, Wq + (long)l*DMODEL*DMODEL, bq + l*DMODEL, p_q,
             BATCH*Lq, DMODEL, DMODEL, DMODEL, DMODEL, DMODEL,
             0,0,0,0,0,0, 1, 1, 0, 0, QSCALE, QSCALE);
        gemm(kv, Wk + (long)l*DMODEL*DMODEL, bk + l*DMODEL, p_k,
             BATCH*Lk, DMODEL, DMODEL, DMODEL, DMODEL, DMODEL,
             0,0,0,0,0,0, 1, 1, 0, 0, 1.f, 1.f);
        gemm(kv, Wv + (long)l*DMODEL*DMODEL, bv + l*DMODEL, p_v,
             BATCH*Lk, DMODEL, DMODEL, DMODEL, DMODEL, DMODEL,
             0,0,0,0,0,0, 1, 1, 0, 0, 1.f, 1.f);

        // qw = q + s*rw, qq = q + s*rr
        {
            long t = (long)BATCH * Lq * DMODEL;
            addbias2_k<<<(unsigned)((t + 255)/256), 256>>>(p_q, rw + l*DMODEL, rr + l*DMODEL, p_qw, p_qq, t);
        }
        // token-type biases
        {
            int t = BATCH * NHEADS * Lq;
            ttb_k<<<(t + 255)/256, 256>>>(p_q, rs + l*DMODEL, sg + (long)l*2*DMODEL, p_t0, p_dt, Lq);
        }

        // content scores: S[b,n,i,j] = sum_h qw * k
        gemm(p_qw, p_k, nullptr, p_S, Lq, Lk, DHEAD,
             DMODEL, DMODEL, Lk,
             (long)Lq*DMODEL, DHEAD, (long)Lk*DMODEL, DHEAD,
             (long)NHEADS*Lq*Lk, (long)Lq*Lk,
             NHEADS, BATCH*NHEADS, 1, 0, 1.f, 0.f);

        // P[b,n,i,u] = sum_h qq * REL[n,h,u]
        gemm(p_qq, p_REL, nullptr, p_P, Lq, nU, DHEAD,
             DMODEL, nU, nU,
             (long)Lq*DMODEL, DHEAD, 0, (long)DHEAD*nU,
             (long)NHEADS*Lq*nU, (long)Lq*nU,
             NHEADS, BATCH*NHEADS, 0, 0, 1.f, 0.f);

        // assemble + softmax (in place over g_S)
        {
            dim3 grid(Lq, NHEADS, BATCH);
            softmax_k<<<grid, 256>>>(p_S, p_P, p_t0, p_dt, tok_ids,
                                     Lq, Lk, nU, cq, ck, u0, pq, pk);
        }

        // vec = prob @ v
        gemm(p_S, p_v, nullptr, p_vec, Lq, DHEAD, Lk,
             Lk, DMODEL, DMODEL,
             (long)NHEADS*Lq*Lk, (long)Lq*Lk, (long)Lk*DMODEL, DHEAD,
             (long)Lq*DMODEL, DHEAD,
             NHEADS, BATCH*NHEADS, 0, 0, 1.f, 0.f);

        // post projection
        gemm(p_vec, Wp + (long)l*DMODEL*DMODEL, bp + l*DMODEL, p_tmp,
             BATCH*Lq, DMODEL, DMODEL, DMODEL, DMODEL, DMODEL,
             0,0,0,0,0,0, 1, 1, 0, 0, 1.f, 1.f);

        // residual + LayerNorm
        float* dst = (l == 0) ? out : bufs[pb];
        ln_k<<<BATCH*Lq, 256>>>(q_in, p_tmp, lg + l*DMODEL, lb + l*DMODEL, dst);

        hidden = dst;
        pb ^= 1;
    }
}

// round 2
// speedup vs baseline: 1.5362x; 1.5362x over previous
#include <cuda_runtime.h>
#include <math.h>
#include <stdint.h>

#define NHEADS 16
#define DHEAD  64
#define DMODEL 1024
#define BATCH  2
#define QSCALE 0.125f
#define MAXTOK 1024
#define NU1 2047
#define NU2 1023
#define NU3 511
#define LNEPS 1e-9f

// ---------------- device scratch (static: no allocations allowed) ----------------
__device__ float g_q  [BATCH*MAXTOK*DMODEL];
__device__ float g_k  [BATCH*MAXTOK*DMODEL];
__device__ float g_v  [BATCH*MAXTOK*DMODEL];
__device__ float g_qw [BATCH*MAXTOK*DMODEL];
__device__ float g_qq [BATCH*MAXTOK*DMODEL];
__device__ float g_vec[BATCH*MAXTOK*DMODEL];
__device__ float g_tmp[BATCH*MAXTOK*DMODEL];
__device__ float g_hA [BATCH*MAXTOK*DMODEL];
__device__ float g_hB [BATCH*MAXTOK*DMODEL];
__device__ float g_up [BATCH*MAXTOK*DMODEL];
__device__ float g_S  [(size_t)BATCH*NHEADS*MAXTOK*MAXTOK];   // scores / probs
__device__ float g_P  [(size_t)BATCH*NHEADS*MAXTOK*NU1];      // rel-pos projections
__device__ float g_REL[NHEADS*DHEAD*NU1];
__device__ float g_rkT[NHEADS*DHEAD*DMODEL];
__device__ float g_R1 [NU1*DMODEL];
__device__ float g_R2 [NU2*DMODEL];
__device__ float g_R3 [NU3*DMODEL];
__device__ float g_tt0[BATCH*NHEADS*MAXTOK];
__device__ float g_dtt[BATCH*NHEADS*MAXTOK];

// ---------------- reductions ----------------
__device__ __forceinline__ float blockReduceSum(float v, float* red) {
    __syncthreads();
    #pragma unroll
    for (int o = 16; o > 0; o >>= 1) v += __shfl_down_sync(0xffffffffu, v, o);
    int lane = threadIdx.x & 31, w = threadIdx.x >> 5;
    if (lane == 0) red[w] = v;
    __syncthreads();
    int nw = (blockDim.x + 31) >> 5;
    if (w == 0) {
        v = (lane < nw) ? red[lane] : 0.f;
        #pragma unroll
        for (int o = 16; o > 0; o >>= 1) v += __shfl_down_sync(0xffffffffu, v, o);
        if (lane == 0) red[0] = v;
    }
    __syncthreads();
    return red[0];
}

__device__ __forceinline__ float blockReduceMax(float v, float* red) {
    __syncthreads();
    #pragma unroll
    for (int o = 16; o > 0; o >>= 1) v = fmaxf(v, __shfl_down_sync(0xffffffffu, v, o));
    int lane = threadIdx.x & 31, w = threadIdx.x >> 5;
    if (lane == 0) red[w] = v;
    __syncthreads();
    int nw = (blockDim.x + 31) >> 5;
    if (w == 0) {
        v = (lane < nw) ? red[lane] : -1e30f;
        #pragma unroll
        for (int o = 16; o > 0; o >>= 1) v = fmaxf(v, __shfl_down_sync(0xffffffffu, v, o));
        if (lane == 0) red[0] = v;
    }
    __syncthreads();
    return red[0];
}

// ---------------- tf32 helpers ----------------
__device__ __forceinline__ void split_tf32(float v, uint32_t& hi, uint32_t& lo) {
    uint32_t h;
    asm("cvt.rna.tf32.f32 %0, %1;" : "=r"(h) : "f"(v));
    float r = v - __uint_as_float(h);
    uint32_t l;
    asm("cvt.rna.tf32.f32 %0, %1;" : "=r"(l) : "f"(r));
    hi = h; lo = l;
}

__device__ __forceinline__ void mma8(float c[4], const uint32_t a[4], const uint32_t b[2]) {
    asm volatile(
        "mma.sync.aligned.m16n8k8.row.col.f32.tf32.tf32.f32 "
        "{%0,%1,%2,%3}, {%4,%5,%6,%7}, {%8,%9}, {%0,%1,%2,%3};"
        : "+f"(c[0]), "+f"(c[1]), "+f"(c[2]), "+f"(c[3])
        : "r"(a[0]), "r"(a[1]), "r"(a[2]), "r"(a[3]), "r"(b[0]), "r"(b[1]));
}

// ---------------- tensor-core batched strided GEMM (3xTF32, near-fp32 accuracy) ----
// C = alpha * A @ op(B) (+ biasAlpha*bias[col]) (+= C if accum)
// batch bz = bo*innerCount + bi ; per-matrix base offset = bo*xO + bi*xI
#define TSTR 136

__global__ __launch_bounds__(256, 1)
void gemm_tc(const float* __restrict__ A, const float* __restrict__ Bm,
             const float* __restrict__ bias, float* __restrict__ C,
             int M, int N, int K, int lda, int ldb, int ldc,
             long aO, long aI, long bO, long bI, long cO, long cI,
             int innerCount, int transB, int accum,
             float alpha, float biasAlpha)
{
    int bz = blockIdx.z;
    int bo = bz / innerCount, bi = bz % innerCount;
    A  += bo * aO + bi * aI;
    Bm += bo * bO + bi * bI;
    C  += bo * cO + bi * cI;

    __shared__ uint32_t Ah[16][TSTR], Al[16][TSTR];
    __shared__ uint32_t Bh[16][TSTR], Bl[16][TSTR];

    int tid  = threadIdx.x;
    int lane = tid & 31, warp = tid >> 5;
    int wm = warp & 1, wn = warp >> 1;      // 2 x 4 warp grid (64 x 32 tiles)
    int gid = lane >> 2, tig = lane & 3;
    int rowBase = blockIdx.y * 128;
    int colBase = blockIdx.x * 128;

    float acc[4][4][4];
    #pragma unroll
    for (int a = 0; a < 4; a++)
        #pragma unroll
        for (int b = 0; b < 4; b++)
            #pragma unroll
            for (int c = 0; c < 4; c++) acc[a][b][c] = 0.f;

    float pa[8], pb[8];
    // prefetch first K-tile
    #pragma unroll
    for (int e = 0; e < 8; e++) {
        int idx = tid + e * 256;
        {
            int m = idx >> 4, kk = idx & 15;
            int gm = rowBase + m, gk = kk;
            pa[e] = (gm < M && gk < K) ? A[(long)gm * lda + gk] : 0.f;
        }
        {
            int kk = idx >> 7, n = idx & 127;
            int gk = kk, gn = colBase + n;
            float v = 0.f;
            if (gk < K && gn < N)
                v = transB ? Bm[(long)gn * ldb + gk] : Bm[(long)gk * ldb + gn];
            pb[e] = v;
        }
    }

    for (int k0 = 0; k0 < K; k0 += 16) {
        __syncthreads();
        #pragma unroll
        for (int e = 0; e < 8; e++) {
            int idx = tid + e * 256;
            {
                int m = idx >> 4, kk = idx & 15;
                uint32_t h, l; split_tf32(pa[e], h, l);
                Ah[kk][m] = h; Al[kk][m] = l;
            }
            {
                int kk = idx >> 7, n = idx & 127;
                uint32_t h, l; split_tf32(pb[e], h, l);
                Bh[kk][n] = h; Bl[kk][n] = l;
            }
        }
        __syncthreads();

        int kn = k0 + 16;
        if (kn < K) {
            #pragma unroll
            for (int e = 0; e < 8; e++) {
                int idx = tid + e * 256;
                {
                    int m = idx >> 4, kk = idx & 15;
                    int gm = rowBase + m, gk = kn + kk;
                    pa[e] = (gm < M && gk < K) ? A[(long)gm * lda + gk] : 0.f;
                }
                {
                    int kk = idx >> 7, n = idx & 127;
                    int gk = kn + kk, gn = colBase + n;
                    float v = 0.f;
                    if (gk < K && gn < N)
                        v = transB ? Bm[(long)gn * ldb + gk] : Bm[(long)gk * ldb + gn];
                    pb[e] = v;
                }
            }
        }

        #pragma unroll
        for (int ks = 0; ks < 16; ks += 8) {
            uint32_t afh[4][4], afl[4][4];
            #pragma unroll
            for (int mi = 0; mi < 4; mi++) {
                int rm = wm * 64 + mi * 16;
                afh[mi][0] = Ah[ks + tig    ][rm + gid];
                afh[mi][1] = Ah[ks + tig    ][rm + gid + 8];
                afh[mi][2] = Ah[ks + tig + 4][rm + gid];
                afh[mi][3] = Ah[ks + tig + 4][rm + gid + 8];
                afl[mi][0] = Al[ks + tig    ][rm + gid];
                afl[mi][1] = Al[ks + tig    ][rm + gid + 8];
                afl[mi][2] = Al[ks + tig + 4][rm + gid];
                afl[mi][3] = Al[ks + tig + 4][rm + gid + 8];
            }
            uint32_t bfh[4][2], bfl[4][2];
            #pragma unroll
            for (int ni = 0; ni < 4; ni++) {
                int cn = wn * 32 + ni * 8;
                bfh[ni][0] = Bh[ks + tig    ][cn + gid];
                bfh[ni][1] = Bh[ks + tig + 4][cn + gid];
                bfl[ni][0] = Bl[ks + tig    ][cn + gid];
                bfl[ni][1] = Bl[ks + tig + 4][cn + gid];
            }
            #pragma unroll
            for (int mi = 0; mi < 4; mi++)
                #pragma unroll
                for (int ni = 0; ni < 4; ni++) {
                    mma8(acc[mi][ni], afh[mi], bfh[ni]);
                    mma8(acc[mi][ni], afh[mi], bfl[ni]);
                    mma8(acc[mi][ni], afl[mi], bfh[ni]);
                }
        }
    }

    // epilogue
    #pragma unroll
    for (int mi = 0; mi < 4; mi++) {
        int r0 = rowBase + wm * 64 + mi * 16 + gid;
        int r1 = r0 + 8;
        #pragma unroll
        for (int ni = 0; ni < 4; ni++) {
            int c0 = colBase + wn * 32 + ni * 8 + tig * 2;
            int c1 = c0 + 1;
            #pragma unroll
            for (int q = 0; q < 4; q++) {
                int gm = (q < 2) ? r0 : r1;
                int gn = (q & 1) ? c1 : c0;
                if (gm < M && gn < N) {
                    float v = alpha * acc[mi][ni][q];
                    if (bias) v += biasAlpha * bias[gn];
                    long off = (long)gm * ldc + gn;
                    if (accum) v += C[off];
                    C[off] = v;
                }
            }
        }
    }
}

// ---------------- relative-position basis: rel(pos,d) ----------------
__global__ void relmat_k(float* __restrict__ R, int nU, int g, int d0)
{
    long idx = (long)blockIdx.x * blockDim.x + threadIdx.x;
    long tot = (long)nU * DMODEL;
    if (idx >= tot) return;
    int u = (int)(idx / DMODEL), d = (int)(idx % DMODEL);
    int f = (d < 512) ? d : d - 512;
    float invf = expf(-(float)f * (9.210340371976184f / 512.0f)); // 10000^(-f/512)
    float arg = (float)(g * u + d0) * invf;
    R[idx] = (d < 512) ? sinf(arg) : cosf(arg);
}

// transpose r_kernel (D, NH, DH) -> (NH*DH, D)
__global__ void rkT_k(const float* __restrict__ rk, float* __restrict__ rkT)
{
    int idx = blockIdx.x * blockDim.x + threadIdx.x;
    if (idx >= DMODEL * NHEADS * DHEAD) return;
    int d = idx / (NHEADS * DHEAD), nh = idx % (NHEADS * DHEAD);
    rkT[(long)nh * DMODEL + d] = rk[idx];
}

// qw = q + SCALE*rw[d], qq = q + SCALE*rr[d]
__global__ void addbias2_k(const float* __restrict__ q, const float* __restrict__ rw,
                           const float* __restrict__ rr, float* __restrict__ qw,
                           float* __restrict__ qq, long total)
{
    long i = (long)blockIdx.x * blockDim.x + threadIdx.x;
    if (i >= total) return;
    int d = (int)(i % DMODEL);
    float v = q[i];
    qw[i] = v + QSCALE * rw[d];
    qq[i] = v + QSCALE * rr[d];
}

// token-type biases: ttb0 and (ttb1-ttb0) per (b,n,i)
__global__ void ttb_k(const float* __restrict__ q, const float* __restrict__ rs,
                      const float* __restrict__ seg, float* __restrict__ tt0,
                      float* __restrict__ dtt, int Lq)
{
    int idx = blockIdx.x * blockDim.x + threadIdx.x;
    if (idx >= BATCH * NHEADS * Lq) return;
    int i = idx % Lq; int bn = idx / Lq; int n = bn % NHEADS; int b = bn / NHEADS;
    const float* qp  = q + ((long)(b * Lq + i)) * DMODEL + n * DHEAD;
    const float* rsp = rs + n * DHEAD;
    const float* s0  = seg + n * DHEAD;           // seg[l][0][n][:]
    const float* s1  = seg + DMODEL + n * DHEAD;  // seg[l][1][n][:]
    float t0 = 0.f, t1 = 0.f;
    #pragma unroll 8
    for (int h = 0; h < DHEAD; h++) {
        float v = qp[h] + QSCALE * rsp[h];
        t0 += v * s0[h];
        t1 += v * s1[h];
    }
    tt0[(long)bn * Lq + i] = t0;
    dtt[(long)bn * Lq + i] = t1 - t0;
}

// assemble scores (content + rel-pos gather + token-type) and softmax in place
__global__ void softmax_k(float* __restrict__ S, const float* __restrict__ P,
                          const float* __restrict__ tt0, const float* __restrict__ dtt,
                          const int* __restrict__ ids,
                          int Lq, int Lk, int nU, int cq, int ck, int u0, int pq, int pk)
{
    int i = blockIdx.x, n = blockIdx.y, b = blockIdx.z;
    int bn = b * NHEADS + n;
    float* Srow = S + ((long)bn * Lq + i) * Lk;
    const float* Prow = P + ((long)bn * Lq + i) * nU;
    float t0 = tt0[(long)bn * Lq + i], dt = dtt[(long)bn * Lq + i];
    const int* idk = ids + b * 1024;
    int idq = idk[pq * i];
    int ubase = cq * i + u0;

    __shared__ float sh[MAXTOK];
    __shared__ float red[32];
    int tid = threadIdx.x;

    float lmax = -1e30f;
    for (int j = tid; j < Lk; j += blockDim.x) {
        float tok = (idk[pk * j] == idq) ? (t0 + dt) : t0;
        float v = Srow[j] + Prow[ubase + ck * j] + tok;
        sh[j] = v;
        lmax = fmaxf(lmax, v);
    }
    float bmax = blockReduceMax(lmax, red);

    float lsum = 0.f;
    for (int j = tid; j < Lk; j += blockDim.x) {
        float e = expf(sh[j] - bmax);
        sh[j] = e;
        lsum += e;
    }
    float bsum = blockReduceSum(lsum, red);
    float inv = 1.0f / bsum;
    for (int j = tid; j < Lk; j += blockDim.x) Srow[j] = sh[j] * inv;
}

// out = LayerNorm(qin + tmp) * g + b
__global__ void ln_k(const float* __restrict__ qin, const float* __restrict__ tmp,
                     const float* __restrict__ gvec, const float* __restrict__ bvec,
                     float* __restrict__ out)
{
    int r = blockIdx.x, tid = threadIdx.x;
    const float* x1 = qin + (long)r * DMODEL;
    const float* x2 = tmp + (long)r * DMODEL;
    __shared__ float red[32];
    float s = 0.f;
    for (int d = tid; d < DMODEL; d += blockDim.x) s += x1[d] + x2[d];
    float mu = blockReduceSum(s, red) * (1.0f / DMODEL);
    float vs = 0.f;
    for (int d = tid; d < DMODEL; d += blockDim.x) {
        float z = x1[d] + x2[d] - mu;
        vs += z * z;
    }
    float var = blockReduceSum(vs, red) * (1.0f / DMODEL);
    float rstd = rsqrtf(var + LNEPS);
    for (int d = tid; d < DMODEL; d += blockDim.x) {
        float z = x1[d] + x2[d] - mu;
        out[(long)r * DMODEL + d] = z * rstd * gvec[d] + bvec[d];
    }
}

// _upsample: out[2t]=h[t], out[2t+1]=0.5*(h[t]+h[t-1 (wrap)])
__global__ void upsample_k(const float* __restrict__ h, float* __restrict__ out, int Lin)
{
    long idx = (long)blockIdx.x * blockDim.x + threadIdx.x;
    long total = (long)BATCH * Lin * DMODEL;
    if (idx >= total) return;
    int d = (int)(idx % DMODEL);
    long bt = idx / DMODEL;
    int t = (int)(bt % Lin);
    int b = (int)(bt / Lin);
    float cur = h[idx];
    int tp = (t == 0) ? Lin - 1 : t - 1;
    float prev = h[((long)b * Lin + tp) * DMODEL + d];
    long ob = ((long)b * (2 * Lin) + 2 * t) * DMODEL + d;
    out[ob] = cur;
    out[ob + DMODEL] = 0.5f * (cur + prev);
}

// ---------------- host ----------------
static void gemm(const float* A, const float* B, const float* bias, float* C,
                 int M, int N, int K, int lda, int ldb, int ldc,
                 long aO, long aI, long bO, long bI, long cO, long cI,
                 int innerCount, int batches, int transB, int accum,
                 float alpha, float biasAlpha)
{
    dim3 grid((N + 127) / 128, (M + 127) / 128, batches);
    gemm_tc<<<grid, 256>>>(A, B, bias, C, M, N, K, lda, ldb, ldc,
                           aO, aI, bO, bI, cO, cI, innerCount, transB, accum,
                           alpha, biasAlpha);
}

extern "C" void kernel_launch(void* const* d_in, const int* in_sizes, int n_in,
                              void* d_out, int out_size)
{
    const float* final_hidden = (const float*)d_in[0];
    const int*   tok_ids      = (const int*)d_in[5];
    const float* Wq = (const float*)d_in[6];
    const float* bq = (const float*)d_in[7];
    const float* Wk = (const float*)d_in[8];
    const float* bk = (const float*)d_in[9];
    const float* Wv = (const float*)d_in[10];
    const float* bv = (const float*)d_in[11];
    const float* rw = (const float*)d_in[12];
    const float* rr = (const float*)d_in[13];
    const float* rs = (const float*)d_in[14];
    const float* rk = (const float*)d_in[15];
    const float* sg = (const float*)d_in[16];
    const float* Wp = (const float*)d_in[17];
    const float* bp = (const float*)d_in[18];
    const float* lg = (const float*)d_in[19];
    const float* lb = (const float*)d_in[20];
    float* out = (float*)d_out;

    float *p_q,*p_k,*p_v,*p_qw,*p_qq,*p_vec,*p_tmp,*p_hA,*p_hB,*p_up;
    float *p_S,*p_P,*p_REL,*p_rkT,*p_R1,*p_R2,*p_R3,*p_t0,*p_dt;
    cudaGetSymbolAddress((void**)&p_q,  g_q);
    cudaGetSymbolAddress((void**)&p_k,  g_k);
    cudaGetSymbolAddress((void**)&p_v,  g_v);
    cudaGetSymbolAddress((void**)&p_qw, g_qw);
    cudaGetSymbolAddress((void**)&p_qq, g_qq);
    cudaGetSymbolAddress((void**)&p_vec,g_vec);
    cudaGetSymbolAddress((void**)&p_tmp,g_tmp);
    cudaGetSymbolAddress((void**)&p_hA, g_hA);
    cudaGetSymbolAddress((void**)&p_hB, g_hB);
    cudaGetSymbolAddress((void**)&p_up, g_up);
    cudaGetSymbolAddress((void**)&p_S,  g_S);
    cudaGetSymbolAddress((void**)&p_P,  g_P);
    cudaGetSymbolAddress((void**)&p_REL,g_REL);
    cudaGetSymbolAddress((void**)&p_rkT,g_rkT);
    cudaGetSymbolAddress((void**)&p_R1, g_R1);
    cudaGetSymbolAddress((void**)&p_R2, g_R2);
    cudaGetSymbolAddress((void**)&p_R3, g_R3);
    cudaGetSymbolAddress((void**)&p_t0, g_tt0);
    cudaGetSymbolAddress((void**)&p_dt, g_dtt);

    // rel-pos basis tables
    {
        long t1 = (long)NU1 * DMODEL;
        relmat_k<<<(unsigned)((t1 + 255) / 256), 256>>>(p_R1, NU1, 1, -1023);
        long t2 = (long)NU2 * DMODEL;
        relmat_k<<<(unsigned)((t2 + 255) / 256), 256>>>(p_R2, NU2, 2, -1022);
        long t3 = (long)NU3 * DMODEL;
        relmat_k<<<(unsigned)((t3 + 255) / 256), 256>>>(p_R3, NU3, 4, -1020);
    }

    const float* hidden = final_hidden;
    float* bufs[2] = {p_hA, p_hB};
    int pb = 0;

    for (int l = 11; l >= 0; --l) {
        int Lq, Lk, do_up, nU, cq, ck, u0, pq, pk; float* R;
        if (l <= 3)      { Lq=1024; Lk=1024; do_up=0; nU=NU1; R=p_R1; cq= 1; ck=-1; u0=1023; pq=1; pk=1; }
        else if (l == 4) { Lq=1024; Lk=512;  do_up=1; nU=NU1; R=p_R1; cq=-1; ck= 2; u0=1023; pq=1; pk=2; }
        else if (l <= 7) { Lq=512;  Lk=512;  do_up=0; nU=NU2; R=p_R2; cq= 1; ck=-1; u0=511;  pq=2; pk=2; }
        else if (l == 8) { Lq=512;  Lk=256;  do_up=1; nU=NU2; R=p_R2; cq=-1; ck= 2; u0=511;  pq=2; pk=4; }
        else             { Lq=256;  Lk=256;  do_up=0; nU=NU3; R=p_R3; cq= 1; ck=-1; u0=255;  pq=4; pk=4; }

        // upsample captured at block ENTRY
        if (l == 11) { long t = (long)BATCH * 256 * DMODEL; upsample_k<<<(unsigned)((t+255)/256), 256>>>(hidden, p_up, 256); }
        if (l == 7)  { long t = (long)BATCH * 512 * DMODEL; upsample_k<<<(unsigned)((t+255)/256), 256>>>(hidden, p_up, 512); }

        const float* q_in = do_up ? p_up : hidden;
        const float* kv = hidden;

        // REL[n,h,u] = sum_d rk[d,n,h] * relbasis[u,d]
        rkT_k<<<(DMODEL*NHEADS*DHEAD + 255)/256, 256>>>(rk + (long)l*DMODEL*NHEADS*DHEAD, p_rkT);
        gemm(p_rkT, R, nullptr, p_REL, DHEAD, nU, DMODEL,
             DMODEL, DMODEL, nU,
             0, (long)DHEAD*DMODEL, 0, 0, 0, (long)DHEAD*nU,
             NHEADS, NHEADS, 1, 0, 1.f, 0.f);

        // projections
        gemm(q_in, Wq + (long)l*DMODEL*DMODEL, bq + l*DMODEL, p_q,
             BATCH*Lq, DMODEL, DMODEL, DMODEL, DMODEL, DMODEL,
             0,0,0,0,0,0, 1, 1, 0, 0, QSCALE, QSCALE);
        gemm(kv, Wk + (long)l*DMODEL*DMODEL, bk + l*DMODEL, p_k,
             BATCH*Lk, DMODEL, DMODEL, DMODEL, DMODEL, DMODEL,
             0,0,0,0,0,0, 1, 1, 0, 0, 1.f, 1.f);
        gemm(kv, Wv + (long)l*DMODEL*DMODEL, bv + l*DMODEL, p_v,
             BATCH*Lk, DMODEL, DMODEL, DMODEL, DMODEL, DMODEL,
             0,0,0,0,0,0, 1, 1, 0, 0, 1.f, 1.f);

        // qw = q + s*rw, qq = q + s*rr
        {
            long t = (long)BATCH * Lq * DMODEL;
            addbias2_k<<<(unsigned)((t + 255)/256), 256>>>(p_q, rw + l*DMODEL, rr + l*DMODEL, p_qw, p_qq, t);
        }
        // token-type biases
        {
            int t = BATCH * NHEADS * Lq;
            ttb_k<<<(t + 255)/256, 256>>>(p_q, rs + l*DMODEL, sg + (long)l*2*DMODEL, p_t0, p_dt, Lq);
        }

        // content scores: S[b,n,i,j] = sum_h qw * k
        gemm(p_qw, p_k, nullptr, p_S, Lq, Lk, DHEAD,
             DMODEL, DMODEL, Lk,
             (long)Lq*DMODEL, DHEAD, (long)Lk*DMODEL, DHEAD,
             (long)NHEADS*Lq*Lk, (long)Lq*Lk,
             NHEADS, BATCH*NHEADS, 1, 0, 1.f, 0.f);

        // P[b,n,i,u] = sum_h qq * REL[n,h,u]
        gemm(p_qq, p_REL, nullptr, p_P, Lq, nU, DHEAD,
             DMODEL, nU, nU,
             (long)Lq*DMODEL, DHEAD, 0, (long)DHEAD*nU,
             (long)NHEADS*Lq*nU, (long)Lq*nU,
             NHEADS, BATCH*NHEADS, 0, 0, 1.f, 0.f);

        // assemble + softmax (in place over g_S)
        {
            dim3 grid(Lq, NHEADS, BATCH);
            softmax_k<<<grid, 256>>>(p_S, p_P, p_t0, p_dt, tok_ids,
                                     Lq, Lk, nU, cq, ck, u0, pq, pk);
        }

        // vec = prob @ v
        gemm(p_S, p_v, nullptr, p_vec, Lq, DHEAD, Lk,
             Lk, DMODEL, DMODEL,
             (long)NHEADS*Lq*Lk, (long)Lq*Lk, (long)Lk*DMODEL, DHEAD,
             (long)Lq*DMODEL, DHEAD,
             NHEADS, BATCH*NHEADS, 0, 0, 1.f, 0.f);

        // post projection
        gemm(p_vec, Wp + (long)l*DMODEL*DMODEL, bp + l*DMODEL, p_tmp,
             BATCH*Lq, DMODEL, DMODEL, DMODEL, DMODEL, DMODEL,
             0,0,0,0,0,0, 1, 1, 0, 0, 1.f, 1.f);

        // residual + LayerNorm
        float* dst = (l == 0) ? out : bufs[pb];
        ln_k<<<BATCH*Lq, 256>>>(q_in, p_tmp, lg + l*DMODEL, lb + l*DMODEL, dst);

        hidden = dst;
        pb ^= 1;
    }
}

// round 4
// speedup vs baseline: 2.0067x; 1.3062x over previous
#include <cuda_runtime.h>
#include <cuda_bf16.h>
#include <math.h>
#include <stdint.h>

#define NHEADS 16
#define DHEAD  64
#define DMODEL 1024
#define BATCH  2
#define QSCALE 0.125f
#define MAXTOK 1024
#define NU1 2047
#define NU2 1023
#define NU3 511
#define LNEPS 1e-9f

// ---------------- device scratch (static: no allocations allowed) ----------------
__device__ float g_q  [BATCH*MAXTOK*DMODEL];
__device__ float g_k  [BATCH*MAXTOK*DMODEL];
__device__ float g_v  [BATCH*MAXTOK*DMODEL];
__device__ float g_qw [BATCH*MAXTOK*DMODEL];
__device__ float g_qq [BATCH*MAXTOK*DMODEL];
__device__ float g_vec[BATCH*MAXTOK*DMODEL];
__device__ float g_tmp[BATCH*MAXTOK*DMODEL];
__device__ float g_hA [BATCH*MAXTOK*DMODEL];
__device__ float g_hB [BATCH*MAXTOK*DMODEL];
__device__ float g_up [BATCH*MAXTOK*DMODEL];
__device__ float g_S  [(size_t)BATCH*NHEADS*MAXTOK*MAXTOK];   // scores / probs
__device__ float g_P  [(size_t)BATCH*NHEADS*MAXTOK*NU1];      // rel-pos projections
__device__ float g_REL[NHEADS*DHEAD*NU1];
__device__ float g_rkT[NHEADS*DHEAD*DMODEL];
__device__ float g_R1 [NU1*DMODEL];
__device__ float g_R2 [NU2*DMODEL];
__device__ float g_R3 [NU3*DMODEL];
__device__ float g_tt0[BATCH*NHEADS*MAXTOK];
__device__ float g_dtt[BATCH*NHEADS*MAXTOK];

// ---------------- reductions ----------------
__device__ __forceinline__ float blockReduceSum(float v, float* red) {
    __syncthreads();
    #pragma unroll
    for (int o = 16; o > 0; o >>= 1) v += __shfl_down_sync(0xffffffffu, v, o);
    int lane = threadIdx.x & 31, w = threadIdx.x >> 5;
    if (lane == 0) red[w] = v;
    __syncthreads();
    int nw = (blockDim.x + 31) >> 5;
    if (w == 0) {
        v = (lane < nw) ? red[lane] : 0.f;
        #pragma unroll
        for (int o = 16; o > 0; o >>= 1) v += __shfl_down_sync(0xffffffffu, v, o);
        if (lane == 0) red[0] = v;
    }
    __syncthreads();
    return red[0];
}

__device__ __forceinline__ float blockReduceMax(float v, float* red) {
    __syncthreads();
    #pragma unroll
    for (int o = 16; o > 0; o >>= 1) v = fmaxf(v, __shfl_down_sync(0xffffffffu, v, o));
    int lane = threadIdx.x & 31, w = threadIdx.x >> 5;
    if (lane == 0) red[w] = v;
    __syncthreads();
    int nw = (blockDim.x + 31) >> 5;
    if (w == 0) {
        v = (lane < nw) ? red[lane] : -1e30f;
        #pragma unroll
        for (int o = 16; o > 0; o >>= 1) v = fmaxf(v, __shfl_down_sync(0xffffffffu, v, o));
        if (lane == 0) red[0] = v;
    }
    __syncthreads();
    return red[0];
}

// ---------------- bf16 split helpers ----------------
// pack two floats' bf16-high parts / residual-low parts into u32 (x in low 16)
__device__ __forceinline__ void split2(float x0, float x1, uint32_t& hi, uint32_t& lo) {
    __nv_bfloat16 h0 = __float2bfloat16_rn(x0);
    __nv_bfloat16 h1 = __float2bfloat16_rn(x1);
    float r0 = x0 - __bfloat162float(h0);
    float r1 = x1 - __bfloat162float(h1);
    __nv_bfloat162 hp; hp.x = h0; hp.y = h1;
    __nv_bfloat162 lp = __floats2bfloat162_rn(r0, r1);
    hi = *reinterpret_cast<uint32_t*>(&hp);
    lo = *reinterpret_cast<uint32_t*>(&lp);
}

__device__ __forceinline__ void mma16(float c[4], const uint32_t a[4], const uint32_t b[2]) {
    asm volatile(
        "mma.sync.aligned.m16n8k16.row.col.f32.bf16.bf16.f32 "
        "{%0,%1,%2,%3}, {%4,%5,%6,%7}, {%8,%9}, {%0,%1,%2,%3};"
        : "+f"(c[0]), "+f"(c[1]), "+f"(c[2]), "+f"(c[3])
        : "r"(a[0]), "r"(a[1]), "r"(a[2]), "r"(a[3]), "r"(b[0]), "r"(b[1]));
}

// ---------------- tensor-core batched strided GEMM (3xBF16, near-fp32 accuracy) ----
// C = alpha * A @ op(B) (+ biasAlpha*bias[col]) (+= C if accum)
// batch bz = bo*innerCount + bi ; per-matrix base offset = bo*xO + bi*xI
#define TSTR 136

__global__ __launch_bounds__(256, 1)
void gemm_tc(const float* __restrict__ A, const float* __restrict__ Bm,
             const float* __restrict__ bias, float* __restrict__ C,
             int M, int N, int K, int lda, int ldb, int ldc,
             long aO, long aI, long bO, long bI, long cO, long cI,
             int innerCount, int transB, int accum,
             float alpha, float biasAlpha)
{
    int bz = blockIdx.z;
    int bo = bz / innerCount, bi = bz % innerCount;
    A  += bo * aO + bi * aI;
    Bm += bo * bO + bi * bI;
    C  += bo * cO + bi * cI;

    // packed bf16 pairs along k: [kp][m] / [kp][n], kp = k/2 in 0..7 (K-tile 16)
    __shared__ uint32_t Ah[8][TSTR], Al[8][TSTR];
    __shared__ uint32_t Bh[8][TSTR], Bl[8][TSTR];

    int tid  = threadIdx.x;
    int lane = tid & 31, warp = tid >> 5;
    int wm = warp & 1, wn = warp >> 1;      // 2 x 4 warp grid (64 x 32 tiles)
    int gid = lane >> 2, tig = lane & 3;
    int rowBase = blockIdx.y * 128;
    int colBase = blockIdx.x * 128;

    float acc[4][4][4];
    #pragma unroll
    for (int a = 0; a < 4; a++)
        #pragma unroll
        for (int b = 0; b < 4; b++)
            #pragma unroll
            for (int c = 0; c < 4; c++) acc[a][b][c] = 0.f;

    // prefetch registers: 4 packed entries per thread per matrix, 2 floats each
    float pa0[4], pa1[4], pb0[4], pb1[4];

    #pragma unroll
    for (int e = 0; e < 4; e++) {
        int p = tid + e * 256;
        {
            int m = p >> 3, kp = p & 7;
            int gm = rowBase + m, gk = 2 * kp;
            pa0[e] = (gm < M && gk     < K) ? A[(long)gm * lda + gk]     : 0.f;
            pa1[e] = (gm < M && gk + 1 < K) ? A[(long)gm * lda + gk + 1] : 0.f;
        }
        {
            int kp = p >> 7, n = p & 127;
            int gk = 2 * kp, gn = colBase + n;
            float v0 = 0.f, v1 = 0.f;
            if (gn < N) {
                if (transB) {
                    if (gk     < K) v0 = Bm[(long)gn * ldb + gk];
                    if (gk + 1 < K) v1 = Bm[(long)gn * ldb + gk + 1];
                } else {
                    if (gk     < K) v0 = Bm[(long)gk * ldb + gn];
                    if (gk + 1 < K) v1 = Bm[(long)(gk + 1) * ldb + gn];
                }
            }
            pb0[e] = v0; pb1[e] = v1;
        }
    }

    for (int k0 = 0; k0 < K; k0 += 16) {
        __syncthreads();
        #pragma unroll
        for (int e = 0; e < 4; e++) {
            int p = tid + e * 256;
            {
                int m = p >> 3, kp = p & 7;
                uint32_t h, l; split2(pa0[e], pa1[e], h, l);
                Ah[kp][m] = h; Al[kp][m] = l;
            }
            {
                int kp = p >> 7, n = p & 127;
                uint32_t h, l; split2(pb0[e], pb1[e], h, l);
                Bh[kp][n] = h; Bl[kp][n] = l;
            }
        }
        __syncthreads();

        int kn = k0 + 16;
        if (kn < K) {
            #pragma unroll
            for (int e = 0; e < 4; e++) {
                int p = tid + e * 256;
                {
                    int m = p >> 3, kp = p & 7;
                    int gm = rowBase + m, gk = kn + 2 * kp;
                    pa0[e] = (gm < M && gk     < K) ? A[(long)gm * lda + gk]     : 0.f;
                    pa1[e] = (gm < M && gk + 1 < K) ? A[(long)gm * lda + gk + 1] : 0.f;
                }
                {
                    int kp = p >> 7, n = p & 127;
                    int gk = kn + 2 * kp, gn = colBase + n;
                    float v0 = 0.f, v1 = 0.f;
                    if (gn < N) {
                        if (transB) {
                            if (gk     < K) v0 = Bm[(long)gn * ldb + gk];
                            if (gk + 1 < K) v1 = Bm[(long)gn * ldb + gk + 1];
                        } else {
                            if (gk     < K) v0 = Bm[(long)gk * ldb + gn];
                            if (gk + 1 < K) v1 = Bm[(long)(gk + 1) * ldb + gn];
                        }
                    }
                    pb0[e] = v0; pb1[e] = v1;
                }
            }
        }

        // fragments: m16n8k16 — a0:(gid, kp=tig) a1:(gid+8, tig) a2:(gid, tig+4) a3:(gid+8, tig+4)
        uint32_t afh[4][4], afl[4][4];
        #pragma unroll
        for (int mi = 0; mi < 4; mi++) {
            int rm = wm * 64 + mi * 16;
            afh[mi][0] = Ah[tig    ][rm + gid];
            afh[mi][1] = Ah[tig    ][rm + gid + 8];
            afh[mi][2] = Ah[tig + 4][rm + gid];
            afh[mi][3] = Ah[tig + 4][rm + gid + 8];
            afl[mi][0] = Al[tig    ][rm + gid];
            afl[mi][1] = Al[tig    ][rm + gid + 8];
            afl[mi][2] = Al[tig + 4][rm + gid];
            afl[mi][3] = Al[tig + 4][rm + gid + 8];
        }
        uint32_t bfh[4][2], bfl[4][2];
        #pragma unroll
        for (int ni = 0; ni < 4; ni++) {
            int cn = wn * 32 + ni * 8;
            bfh[ni][0] = Bh[tig    ][cn + gid];
            bfh[ni][1] = Bh[tig + 4][cn + gid];
            bfl[ni][0] = Bl[tig    ][cn + gid];
            bfl[ni][1] = Bl[tig + 4][cn + gid];
        }
        #pragma unroll
        for (int mi = 0; mi < 4; mi++)
            #pragma unroll
            for (int ni = 0; ni < 4; ni++) {
                mma16(acc[mi][ni], afh[mi], bfh[ni]);
                mma16(acc[mi][ni], afh[mi], bfl[ni]);
                mma16(acc[mi][ni], afl[mi], bfh[ni]);
            }
    }

    // epilogue (m16n8 output layout: c0,c1 -> row gid cols 2tig,2tig+1; c2,c3 -> row gid+8)
    #pragma unroll
    for (int mi = 0; mi < 4; mi++) {
        int r0 = rowBase + wm * 64 + mi * 16 + gid;
        int r1 = r0 + 8;
        #pragma unroll
        for (int ni = 0; ni < 4; ni++) {
            int c0 = colBase + wn * 32 + ni * 8 + tig * 2;
            int c1 = c0 + 1;
            #pragma unroll
            for (int q = 0; q < 4; q++) {
                int gm = (q < 2) ? r0 : r1;
                int gn = (q & 1) ? c1 : c0;
                if (gm < M && gn < N) {
                    float v = alpha * acc[mi][ni][q];
                    if (bias) v += biasAlpha * bias[gn];
                    long off = (long)gm * ldc + gn;
                    if (accum) v += C[off];
                    C[off] = v;
                }
            }
        }
    }
}

// ---------------- relative-position basis: rel(pos,d) ----------------
__global__ void relmat_k(float* __restrict__ R, int nU, int g, int d0)
{
    long idx = (long)blockIdx.x * blockDim.x + threadIdx.x;
    long tot = (long)nU * DMODEL;
    if (idx >= tot) return;
    int u = (int)(idx / DMODEL), d = (int)(idx % DMODEL);
    int f = (d < 512) ? d : d - 512;
    float invf = expf(-(float)f * (9.210340371976184f / 512.0f)); // 10000^(-f/512)
    float arg = (float)(g * u + d0) * invf;
    R[idx] = (d < 512) ? sinf(arg) : cosf(arg);
}

// transpose r_kernel (D, NH, DH) -> (NH*DH, D)
__global__ void rkT_k(const float* __restrict__ rk, float* __restrict__ rkT)
{
    int idx = blockIdx.x * blockDim.x + threadIdx.x;
    if (idx >= DMODEL * NHEADS * DHEAD) return;
    int d = idx / (NHEADS * DHEAD), nh = idx % (NHEADS * DHEAD);
    rkT[(long)nh * DMODEL + d] = rk[idx];
}

// qw = q + SCALE*rw[d], qq = q + SCALE*rr[d]
__global__ void addbias2_k(const float* __restrict__ q, const float* __restrict__ rw,
                           const float* __restrict__ rr, float* __restrict__ qw,
                           float* __restrict__ qq, long total)
{
    long i = (long)blockIdx.x * blockDim.x + threadIdx.x;
    if (i >= total) return;
    int d = (int)(i % DMODEL);
    float v = q[i];
    qw[i] = v + QSCALE * rw[d];
    qq[i] = v + QSCALE * rr[d];
}

// token-type biases: ttb0 and (ttb1-ttb0) per (b,n,i)
__global__ void ttb_k(const float* __restrict__ q, const float* __restrict__ rs,
                      const float* __restrict__ seg, float* __restrict__ tt0,
                      float* __restrict__ dtt, int Lq)
{
    int idx = blockIdx.x * blockDim.x + threadIdx.x;
    if (idx >= BATCH * NHEADS * Lq) return;
    int i = idx % Lq; int bn = idx / Lq; int n = bn % NHEADS; int b = bn / NHEADS;
    const float* qp  = q + ((long)(b * Lq + i)) * DMODEL + n * DHEAD;
    const float* rsp = rs + n * DHEAD;
    const float* s0  = seg + n * DHEAD;           // seg[l][0][n][:]
    const float* s1  = seg + DMODEL + n * DHEAD;  // seg[l][1][n][:]
    float t0 = 0.f, t1 = 0.f;
    #pragma unroll 8
    for (int h = 0; h < DHEAD; h++) {
        float v = qp[h] + QSCALE * rsp[h];
        t0 += v * s0[h];
        t1 += v * s1[h];
    }
    tt0[(long)bn * Lq + i] = t0;
    dtt[(long)bn * Lq + i] = t1 - t0;
}

// assemble scores (content + rel-pos gather + token-type) and softmax in place
__global__ void softmax_k(float* __restrict__ S, const float* __restrict__ P,
                          const float* __restrict__ tt0, const float* __restrict__ dtt,
                          const int* __restrict__ ids,
                          int Lq, int Lk, int nU, int cq, int ck, int u0, int pq, int pk)
{
    int i = blockIdx.x, n = blockIdx.y, b = blockIdx.z;
    int bn = b * NHEADS + n;
    float* Srow = S + ((long)bn * Lq + i) * Lk;
    const float* Prow = P + ((long)bn * Lq + i) * nU;
    float t0 = tt0[(long)bn * Lq + i], dt = dtt[(long)bn * Lq + i];
    const int* idk = ids + b * 1024;
    int idq = idk[pq * i];
    int ubase = cq * i + u0;

    __shared__ float sh[MAXTOK];
    __shared__ float red[32];
    int tid = threadIdx.x;

    float lmax = -1e30f;
    for (int j = tid; j < Lk; j += blockDim.x) {
        float tok = (idk[pk * j] == idq) ? (t0 + dt) : t0;
        float v = Srow[j] + Prow[ubase + ck * j] + tok;
        sh[j] = v;
        lmax = fmaxf(lmax, v);
    }
    float bmax = blockReduceMax(lmax, red);

    float lsum = 0.f;
    for (int j = tid; j < Lk; j += blockDim.x) {
        float e = expf(sh[j] - bmax);
        sh[j] = e;
        lsum += e;
    }
    float bsum = blockReduceSum(lsum, red);
    float inv = 1.0f / bsum;
    for (int j = tid; j < Lk; j += blockDim.x) Srow[j] = sh[j] * inv;
}

// out = LayerNorm(qin + tmp) * g + b
__global__ void ln_k(const float* __restrict__ qin, const float* __restrict__ tmp,
                     const float* __restrict__ gvec, const float* __restrict__ bvec,
                     float* __restrict__ out)
{
    int r = blockIdx.x, tid = threadIdx.x;
    const float* x1 = qin + (long)r * DMODEL;
    const float* x2 = tmp + (long)r * DMODEL;
    __shared__ float red[32];
    float s = 0.f;
    for (int d = tid; d < DMODEL; d += blockDim.x) s += x1[d] + x2[d];
    float mu = blockReduceSum(s, red) * (1.0f / DMODEL);
    float vs = 0.f;
    for (int d = tid; d < DMODEL; d += blockDim.x) {
        float z = x1[d] + x2[d] - mu;
        vs += z * z;
    }
    float var = blockReduceSum(vs, red) * (1.0f / DMODEL);
    float rstd = rsqrtf(var + LNEPS);
    for (int d = tid; d < DMODEL; d += blockDim.x) {
        float z = x1[d] + x2[d] - mu;
        out[(long)r * DMODEL + d] = z * rstd * gvec[d] + bvec[d];
    }
}

// _upsample: out[2t]=h[t], out[2t+1]=0.5*(h[t]+h[t-1 (wrap)])
__global__ void upsample_k(const float* __restrict__ h, float* __restrict__ out, int Lin)
{
    long idx = (long)blockIdx.x * blockDim.x + threadIdx.x;
    long total = (long)BATCH * Lin * DMODEL;
    if (idx >= total) return;
    int d = (int)(idx % DMODEL);
    long bt = idx / DMODEL;
    int t = (int)(bt % Lin);
    int b = (int)(bt / Lin);
    float cur = h[idx];
    int tp = (t == 0) ? Lin - 1 : t - 1;
    float prev = h[((long)b * Lin + tp) * DMODEL + d];
    long ob = ((long)b * (2 * Lin) + 2 * t) * DMODEL + d;
    out[ob] = cur;
    out[ob + DMODEL] = 0.5f * (cur + prev);
}

// ---------------- host ----------------
static void gemm(const float* A, const float* B, const float* bias, float* C,
                 int M, int N, int K, int lda, int ldb, int ldc,
                 long aO, long aI, long bO, long bI, long cO, long cI,
                 int innerCount, int batches, int transB, int accum,
                 float alpha, float biasAlpha)
{
    dim3 grid((N + 127) / 128, (M + 127) / 128, batches);
    gemm_tc<<<grid, 256>>>(A, B, bias, C, M, N, K, lda, ldb, ldc,
                           aO, aI, bO, bI, cO, cI, innerCount, transB, accum,
                           alpha, biasAlpha);
}

extern "C" void kernel_launch(void* const* d_in, const int* in_sizes, int n_in,
                              void* d_out, int out_size)
{
    const float* final_hidden = (const float*)d_in[0];
    const int*   tok_ids      = (const int*)d_in[5];
    const float* Wq = (const float*)d_in[6];
    const float* bq = (const float*)d_in[7];
    const float* Wk = (const float*)d_in[8];
    const float* bk = (const float*)d_in[9];
    const float* Wv = (const float*)d_in[10];
    const float* bv = (const float*)d_in[11];
    const float* rw = (const float*)d_in[12];
    const float* rr = (const float*)d_in[13];
    const float* rs = (const float*)d_in[14];
    const float* rk = (const float*)d_in[15];
    const float* sg = (const float*)d_in[16];
    const float* Wp = (const float*)d_in[17];
    const float* bp = (const float*)d_in[18];
    const float* lg = (const float*)d_in[19];
    const float* lb = (const float*)d_in[20];
    float* out = (float*)d_out;

    float *p_q,*p_k,*p_v,*p_qw,*p_qq,*p_vec,*p_tmp,*p_hA,*p_hB,*p_up;
    float *p_S,*p_P,*p_REL,*p_rkT,*p_R1,*p_R2,*p_R3,*p_t0,*p_dt;
    cudaGetSymbolAddress((void**)&p_q,  g_q);
    cudaGetSymbolAddress((void**)&p_k,  g_k);
    cudaGetSymbolAddress((void**)&p_v,  g_v);
    cudaGetSymbolAddress((void**)&p_qw, g_qw);
    cudaGetSymbolAddress((void**)&p_qq, g_qq);
    cudaGetSymbolAddress((void**)&p_vec,g_vec);
    cudaGetSymbolAddress((void**)&p_tmp,g_tmp);
    cudaGetSymbolAddress((void**)&p_hA, g_hA);
    cudaGetSymbolAddress((void**)&p_hB, g_hB);
    cudaGetSymbolAddress((void**)&p_up, g_up);
    cudaGetSymbolAddress((void**)&p_S,  g_S);
    cudaGetSymbolAddress((void**)&p_P,  g_P);
    cudaGetSymbolAddress((void**)&p_REL,g_REL);
    cudaGetSymbolAddress((void**)&p_rkT,g_rkT);
    cudaGetSymbolAddress((void**)&p_R1, g_R1);
    cudaGetSymbolAddress((void**)&p_R2, g_R2);
    cudaGetSymbolAddress((void**)&p_R3, g_R3);
    cudaGetSymbolAddress((void**)&p_t0, g_tt0);
    cudaGetSymbolAddress((void**)&p_dt, g_dtt);

    // rel-pos basis tables
    {
        long t1 = (long)NU1 * DMODEL;
        relmat_k<<<(unsigned)((t1 + 255) / 256), 256>>>(p_R1, NU1, 1, -1023);
        long t2 = (long)NU2 * DMODEL;
        relmat_k<<<(unsigned)((t2 + 255) / 256), 256>>>(p_R2, NU2, 2, -1022);
        long t3 = (long)NU3 * DMODEL;
        relmat_k<<<(unsigned)((t3 + 255) / 256), 256>>>(p_R3, NU3, 4, -1020);
    }

    const float* hidden = final_hidden;
    float* bufs[2] = {p_hA, p_hB};
    int pb = 0;

    for (int l = 11; l >= 0; --l) {
        int Lq, Lk, do_up, nU, cq, ck, u0, pq, pk; float* R;
        if (l <= 3)      { Lq=1024; Lk=1024; do_up=0; nU=NU1; R=p_R1; cq= 1; ck=-1; u0=1023; pq=1; pk=1; }
        else if (l == 4) { Lq=1024; Lk=512;  do_up=1; nU=NU1; R=p_R1; cq=-1; ck= 2; u0=1023; pq=1; pk=2; }
        else if (l <= 7) { Lq=512;  Lk=512;  do_up=0; nU=NU2; R=p_R2; cq= 1; ck=-1; u0=511;  pq=2; pk=2; }
        else if (l == 8) { Lq=512;  Lk=256;  do_up=1; nU=NU2; R=p_R2; cq=-1; ck= 2; u0=511;  pq=2; pk=4; }
        else             { Lq=256;  Lk=256;  do_up=0; nU=NU3; R=p_R3; cq= 1; ck=-1; u0=255;  pq=4; pk=4; }

        // upsample captured at block ENTRY
        if (l == 11) { long t = (long)BATCH * 256 * DMODEL; upsample_k<<<(unsigned)((t+255)/256), 256>>>(hidden, p_up, 256); }
        if (l == 7)  { long t = (long)BATCH * 512 * DMODEL; upsample_k<<<(unsigned)((t+255)/256), 256>>>(hidden, p_up, 512); }

        const float* q_in = do_up ? p_up : hidden;
        const float* kv = hidden;

        // REL[n,h,u] = sum_d rk[d,n,h] * relbasis[u,d]
        rkT_k<<<(DMODEL*NHEADS*DHEAD + 255)/256, 256>>>(rk + (long)l*DMODEL*NHEADS*DHEAD, p_rkT);
        gemm(p_rkT, R, nullptr, p_REL, DHEAD, nU, DMODEL,
             DMODEL, DMODEL, nU,
             0, (long)DHEAD*DMODEL, 0, 0, 0, (long)DHEAD*nU,
             NHEADS, NHEADS, 1, 0, 1.f, 0.f);

        // projections
        gemm(q_in, Wq + (long)l*DMODEL*DMODEL, bq + l*DMODEL, p_q,
             BATCH*Lq, DMODEL, DMODEL, DMODEL, DMODEL, DMODEL,
             0,0,0,0,0,0, 1, 1, 0, 0, QSCALE, QSCALE);
        gemm(kv, Wk + (long)l*DMODEL*DMODEL, bk + l*DMODEL, p_k,
             BATCH*Lk, DMODEL, DMODEL, DMODEL, DMODEL, DMODEL,
             0,0,0,0,0,0, 1, 1, 0, 0, 1.f, 1.f);
        gemm(kv, Wv + (long)l*DMODEL*DMODEL, bv + l*DMODEL, p_v,
             BATCH*Lk, DMODEL, DMODEL, DMODEL, DMODEL, DMODEL,
             0,0,0,0,0,0, 1, 1, 0, 0, 1.f, 1.f);

        // qw = q + s*rw, qq = q + s*rr
        {
            long t = (long)BATCH * Lq * DMODEL;
            addbias2_k<<<(unsigned)((t + 255)/256), 256>>>(p_q, rw + l*DMODEL, rr + l*DMODEL, p_qw, p_qq, t);
        }
        // token-type biases
        {
            int t = BATCH * NHEADS * Lq;
            ttb_k<<<(t + 255)/256, 256>>>(p_q, rs + l*DMODEL, sg + (long)l*2*DMODEL, p_t0, p_dt, Lq);
        }

        // content scores: S[b,n,i,j] = sum_h qw * k
        gemm(p_qw, p_k, nullptr, p_S, Lq, Lk, DHEAD,
             DMODEL, DMODEL, Lk,
             (long)Lq*DMODEL, DHEAD, (long)Lk*DMODEL, DHEAD,
             (long)NHEADS*Lq*Lk, (long)Lq*Lk,
             NHEADS, BATCH*NHEADS, 1, 0, 1.f, 0.f);

        // P[b,n,i,u] = sum_h qq * REL[n,h,u]
        gemm(p_qq, p_REL, nullptr, p_P, Lq, nU, DHEAD,
             DMODEL, nU, nU,
             (long)Lq*DMODEL, DHEAD, 0, (long)DHEAD*nU,
             (long)NHEADS*Lq*nU, (long)Lq*nU,
             NHEADS, BATCH*NHEADS, 0, 0, 1.f, 0.f);

        // assemble + softmax (in place over g_S)
        {
            dim3 grid(Lq, NHEADS, BATCH);
            softmax_k<<<grid, 256>>>(p_S, p_P, p_t0, p_dt, tok_ids,
                                     Lq, Lk, nU, cq, ck, u0, pq, pk);
        }

        // vec = prob @ v
        gemm(p_S, p_v, nullptr, p_vec, Lq, DHEAD, Lk,
             Lk, DMODEL, DMODEL,
             (long)NHEADS*Lq*Lk, (long)Lq*Lk, (long)Lk*DMODEL, DHEAD,
             (long)Lq*DMODEL, DHEAD,
             NHEADS, BATCH*NHEADS, 0, 0, 1.f, 0.f);

        // post projection
        gemm(p_vec, Wp + (long)l*DMODEL*DMODEL, bp + l*DMODEL, p_tmp,
             BATCH*Lq, DMODEL, DMODEL, DMODEL, DMODEL, DMODEL,
             0,0,0,0,0,0, 1, 1, 0, 0, 1.f, 1.f);

        // residual + LayerNorm
        float* dst = (l == 0) ? out : bufs[pb];
        ln_k<<<BATCH*Lq, 256>>>(q_in, p_tmp, lg + l*DMODEL, lb + l*DMODEL, dst);

        hidden = dst;
        pb ^= 1;
    }
}

// round 5
// speedup vs baseline: 2.7909x; 1.3908x over previous
#include <cuda_runtime.h>
#include <cuda_bf16.h>
#include <math.h>
#include <stdint.h>

#define NHEADS 16
#define DHEAD  64
#define DMODEL 1024
#define BATCH  2
#define QSCALE 0.125f
#define MAXTOK 1024
#define NU1 2047
#define NU2 1023
#define NU3 511
#define NUP1 2048
#define LNEPS 1e-9f
#define SLACK 4096

// ---------------- float scratch ----------------
__device__ float g_q  [BATCH*MAXTOK*DMODEL];
__device__ float g_k  [BATCH*MAXTOK*DMODEL];
__device__ float g_v  [BATCH*MAXTOK*DMODEL];
__device__ float g_tmp[BATCH*MAXTOK*DMODEL];
__device__ float g_hA [BATCH*MAXTOK*DMODEL];
__device__ float g_hB [BATCH*MAXTOK*DMODEL];
__device__ float g_up [BATCH*MAXTOK*DMODEL];
__device__ float g_S  [(size_t)BATCH*NHEADS*MAXTOK*MAXTOK];
__device__ float g_P  [(size_t)BATCH*NHEADS*MAXTOK*NU1];
__device__ float g_REL[NHEADS*DHEAD*NU1];
__device__ float g_R1 [NU1*DMODEL];
__device__ float g_R2 [NU2*DMODEL];
__device__ float g_R3 [NU3*DMODEL];
__device__ float g_tt0[BATCH*NHEADS*MAXTOK];
__device__ float g_dtt[BATCH*NHEADS*MAXTOK];

// ---------------- split scratch (u32 = packed bf16 pair along k) ----------------
#define WSPL (12*512*1024)
__device__ __align__(16) uint32_t g_Wqh[WSPL+SLACK], g_Wql[WSPL+SLACK];
__device__ __align__(16) uint32_t g_Wkh[WSPL+SLACK], g_Wkl[WSPL+SLACK];
__device__ __align__(16) uint32_t g_Wvh[WSPL+SLACK], g_Wvl[WSPL+SLACK];
__device__ __align__(16) uint32_t g_Wph[WSPL+SLACK], g_Wpl[WSPL+SLACK];
__device__ __align__(16) uint32_t g_R1h[512*NUP1+SLACK], g_R1l[512*NUP1+SLACK];
__device__ __align__(16) uint32_t g_R2h[512*1024+SLACK], g_R2l[512*1024+SLACK];
__device__ __align__(16) uint32_t g_R3h[512*512+SLACK],  g_R3l[512*512+SLACK];
__device__ __align__(16) uint32_t g_rkTh[1024*512+SLACK], g_rkTl[1024*512+SLACK];
__device__ __align__(16) uint32_t g_RELh[16*32*NUP1+SLACK], g_RELl[16*32*NUP1+SLACK];
__device__ __align__(16) uint32_t g_ksh[2*512*1024+SLACK], g_ksl[2*512*1024+SLACK];
__device__ __align__(16) uint32_t g_vsh[2*512*1024+SLACK], g_vsl[2*512*1024+SLACK];
__device__ __align__(16) uint32_t g_qwh[BATCH*MAXTOK*512+SLACK], g_qwl[BATCH*MAXTOK*512+SLACK];
__device__ __align__(16) uint32_t g_qqh[BATCH*MAXTOK*512+SLACK], g_qql[BATCH*MAXTOK*512+SLACK];
__device__ __align__(16) uint32_t g_Ssh[(size_t)BATCH*NHEADS*MAXTOK*512+SLACK];
__device__ __align__(16) uint32_t g_Ssl[(size_t)BATCH*NHEADS*MAXTOK*512+SLACK];
__device__ __align__(16) uint32_t g_vch[BATCH*MAXTOK*512+SLACK], g_vcl[BATCH*MAXTOK*512+SLACK];
__device__ __align__(16) uint32_t g_hsh[BATCH*MAXTOK*512+SLACK], g_hsl[BATCH*MAXTOK*512+SLACK];
__device__ __align__(16) uint32_t g_ush[BATCH*MAXTOK*512+SLACK], g_usl[BATCH*MAXTOK*512+SLACK];

// ---------------- helpers ----------------
__device__ __forceinline__ uint32_t pack_hi(float x0, float x1, uint32_t& lo) {
    __nv_bfloat16 h0 = __float2bfloat16_rn(x0);
    __nv_bfloat16 h1 = __float2bfloat16_rn(x1);
    float r0 = x0 - __bfloat162float(h0);
    float r1 = x1 - __bfloat162float(h1);
    __nv_bfloat162 hp; hp.x = h0; hp.y = h1;
    __nv_bfloat162 lp = __floats2bfloat162_rn(r0, r1);
    lo = *reinterpret_cast<uint32_t*>(&lp);
    return *reinterpret_cast<uint32_t*>(&hp);
}

__device__ __forceinline__ void mma16(float c[4], const uint32_t a[4], const uint32_t b[2]) {
    asm volatile(
        "mma.sync.aligned.m16n8k16.row.col.f32.bf16.bf16.f32 "
        "{%0,%1,%2,%3}, {%4,%5,%6,%7}, {%8,%9}, {%0,%1,%2,%3};"
        : "+f"(c[0]), "+f"(c[1]), "+f"(c[2]), "+f"(c[3])
        : "r"(a[0]), "r"(a[1]), "r"(a[2]), "r"(a[3]), "r"(b[0]), "r"(b[1]));
}

__device__ __forceinline__ float blockReduceSum(float v, float* red) {
    __syncthreads();
    #pragma unroll
    for (int o = 16; o > 0; o >>= 1) v += __shfl_down_sync(0xffffffffu, v, o);
    int lane = threadIdx.x & 31, w = threadIdx.x >> 5;
    if (lane == 0) red[w] = v;
    __syncthreads();
    int nw = (blockDim.x + 31) >> 5;
    if (w == 0) {
        v = (lane < nw) ? red[lane] : 0.f;
        #pragma unroll
        for (int o = 16; o > 0; o >>= 1) v += __shfl_down_sync(0xffffffffu, v, o);
        if (lane == 0) red[0] = v;
    }
    __syncthreads();
    return red[0];
}
__device__ __forceinline__ float blockReduceMax(float v, float* red) {
    __syncthreads();
    #pragma unroll
    for (int o = 16; o > 0; o >>= 1) v = fmaxf(v, __shfl_down_sync(0xffffffffu, v, o));
    int lane = threadIdx.x & 31, w = threadIdx.x >> 5;
    if (lane == 0) red[w] = v;
    __syncthreads();
    int nw = (blockDim.x + 31) >> 5;
    if (w == 0) {
        v = (lane < nw) ? red[lane] : -1e30f;
        #pragma unroll
        for (int o = 16; o > 0; o >>= 1) v = fmaxf(v, __shfl_down_sync(0xffffffffu, v, o));
        if (lane == 0) red[0] = v;
    }
    __syncthreads();
    return red[0];
}

// ---------------- unified split-input tensor-core GEMM (3xBF16) ----------------
// A split: [M][Kp] u32 (k-pairs contiguous), B split: [Kp][N] u32.
// C float optional; Ch/Cl split output optional (packs adjacent column pairs).
#define ASTR 12
#define TSTR 136

__global__ __launch_bounds__(256, 1)
void gemm_tcs(const uint32_t* __restrict__ Ah_, const uint32_t* __restrict__ Al_,
              const uint32_t* __restrict__ Bh_, const uint32_t* __restrict__ Bl_,
              const float* __restrict__ bias, float* __restrict__ C,
              uint32_t* __restrict__ Ch, uint32_t* __restrict__ Cl,
              int M, int N, int Kp, int ldau, int ldbu, int ldc, int ldcs,
              long aO, long aI, long bO, long bI, long cO, long cI,
              int innerCount, float alpha, float biasAlpha,
              int posWin, int pcq, int pck, int pu0, int pLk)
{
    int rowBase = blockIdx.y * 128;
    int colBase = blockIdx.x * 128;
    if (posWin) {
        int r0 = rowBase, r1 = min(rowBase + 127, M - 1);
        int t1 = pcq * r0, t2 = pcq * r1;
        int umin = pu0 + min(t1, t2) + min(0, pck * (pLk - 1));
        int umax = pu0 + max(t1, t2) + max(0, pck * (pLk - 1));
        if (colBase > umax || colBase + 127 < umin) return;
    }
    int bz = blockIdx.z;
    int bo = bz / innerCount, bi = bz % innerCount;
    const uint32_t* Ahp = Ah_ + bo * aO + bi * aI;
    const uint32_t* Alp = Al_ + bo * aO + bi * aI;
    const uint32_t* Bhp = Bh_ + bo * bO + bi * bI;
    const uint32_t* Blp = Bl_ + bo * bO + bi * bI;

    __shared__ uint32_t Ash[128][ASTR], Asl[128][ASTR];
    __shared__ uint32_t Bsh[8][TSTR],  Bsl[8][TSTR];

    int tid = threadIdx.x, lane = tid & 31, warp = tid >> 5;
    int wm = warp & 1, wn = warp >> 1;
    int gid = lane >> 2, tig = lane & 3;

    int rowA = tid >> 1, halfA = (tid & 1) * 4;
    int kpB  = tid >> 5, nB = (tid & 31) * 4;
    bool aOk = (rowBase + rowA) < M;
    long aBase = (long)(rowBase + rowA) * ldau + halfA;
    long bBase = (long)kpB * ldbu + colBase + nB;

    float acc[4][4][4];
    #pragma unroll
    for (int a = 0; a < 4; a++)
        #pragma unroll
        for (int b = 0; b < 4; b++)
            #pragma unroll
            for (int c = 0; c < 4; c++) acc[a][b][c] = 0.f;

    uint4 zz = make_uint4(0, 0, 0, 0);
    uint4 ra_h = aOk ? *(const uint4*)(Ahp + aBase) : zz;
    uint4 ra_l = aOk ? *(const uint4*)(Alp + aBase) : zz;
    uint4 rb_h = *(const uint4*)(Bhp + bBase);
    uint4 rb_l = *(const uint4*)(Blp + bBase);

    for (int kp0 = 0; kp0 < Kp; kp0 += 8) {
        __syncthreads();
        *(uint4*)&Ash[rowA][halfA] = ra_h;
        *(uint4*)&Asl[rowA][halfA] = ra_l;
        *(uint4*)&Bsh[kpB][nB]     = rb_h;
        *(uint4*)&Bsl[kpB][nB]     = rb_l;
        __syncthreads();

        int kn = kp0 + 8;
        if (kn < Kp) {
            ra_h = aOk ? *(const uint4*)(Ahp + aBase + kn) : zz;
            ra_l = aOk ? *(const uint4*)(Alp + aBase + kn) : zz;
            rb_h = *(const uint4*)(Bhp + bBase + (long)kn * ldbu);
            rb_l = *(const uint4*)(Blp + bBase + (long)kn * ldbu);
        }

        uint32_t afh[4][4], afl[4][4];
        #pragma unroll
        for (int mi = 0; mi < 4; mi++) {
            int rm = wm * 64 + mi * 16;
            afh[mi][0] = Ash[rm + gid    ][tig];
            afh[mi][1] = Ash[rm + gid + 8][tig];
            afh[mi][2] = Ash[rm + gid    ][tig + 4];
            afh[mi][3] = Ash[rm + gid + 8][tig + 4];
            afl[mi][0] = Asl[rm + gid    ][tig];
            afl[mi][1] = Asl[rm + gid + 8][tig];
            afl[mi][2] = Asl[rm + gid    ][tig + 4];
            afl[mi][3] = Asl[rm + gid + 8][tig + 4];
        }
        uint32_t bfh[4][2], bfl[4][2];
        #pragma unroll
        for (int ni = 0; ni < 4; ni++) {
            int cn = wn * 32 + ni * 8;
            bfh[ni][0] = Bsh[tig    ][cn + gid];
            bfh[ni][1] = Bsh[tig + 4][cn + gid];
            bfl[ni][0] = Bsl[tig    ][cn + gid];
            bfl[ni][1] = Bsl[tig + 4][cn + gid];
        }
        #pragma unroll
        for (int mi = 0; mi < 4; mi++)
            #pragma unroll
            for (int ni = 0; ni < 4; ni++) {
                mma16(acc[mi][ni], afh[mi], bfh[ni]);
                mma16(acc[mi][ni], afh[mi], bfl[ni]);
                mma16(acc[mi][ni], afl[mi], bfh[ni]);
            }
    }

    float*    Cp  = C  ? C  + bo * cO + bi * cI : (float*)0;
    uint32_t* Chp = Ch ? Ch + bo * cO + bi * cI : (uint32_t*)0;
    uint32_t* Clp = Cl ? Cl + bo * cO + bi * cI : (uint32_t*)0;

    #pragma unroll
    for (int mi = 0; mi < 4; mi++) {
        int r0 = rowBase + wm * 64 + mi * 16 + gid;
        int r1 = r0 + 8;
        #pragma unroll
        for (int ni = 0; ni < 4; ni++) {
            int c0 = colBase + wn * 32 + ni * 8 + tig * 2;
            int c1 = c0 + 1;
            float b0 = bias ? biasAlpha * bias[(c0 < N) ? c0 : 0] : 0.f;
            float b1 = bias ? biasAlpha * bias[(c1 < N) ? c1 : 0] : 0.f;
            if (Cp) {
                if (r0 < M && c0 < N) Cp[(long)r0 * ldc + c0] = alpha * acc[mi][ni][0] + b0;
                if (r0 < M && c1 < N) Cp[(long)r0 * ldc + c1] = alpha * acc[mi][ni][1] + b1;
                if (r1 < M && c0 < N) Cp[(long)r1 * ldc + c0] = alpha * acc[mi][ni][2] + b0;
                if (r1 < M && c1 < N) Cp[(long)r1 * ldc + c1] = alpha * acc[mi][ni][3] + b1;
            }
            if (Chp && c0 < N) {
                if (r0 < M) {
                    uint32_t lo, hi = pack_hi(alpha * acc[mi][ni][0] + b0,
                                              alpha * acc[mi][ni][1] + b1, lo);
                    Chp[(long)r0 * ldcs + (c0 >> 1)] = hi;
                    Clp[(long)r0 * ldcs + (c0 >> 1)] = lo;
                }
                if (r1 < M) {
                    uint32_t lo, hi = pack_hi(alpha * acc[mi][ni][2] + b0,
                                              alpha * acc[mi][ni][3] + b1, lo);
                    Chp[(long)r1 * ldcs + (c0 >> 1)] = hi;
                    Clp[(long)r1 * ldcs + (c0 >> 1)] = lo;
                }
            }
        }
    }
}

// ---------------- split kernels ----------------
// B-format split: dst[kp][n] (ld=dstLd) = pack(src[2kp*kStr + n*nStr], src[(2kp+1)*kStr + n*nStr])
__global__ void splitB_k(const float* __restrict__ src, uint32_t* __restrict__ dh,
                         uint32_t* __restrict__ dl, int Kp, int N, int dstLd,
                         long kStr, long nStr, long srcBOff, long dstBOff, int nBatch)
{
    long idx = (long)blockIdx.x * blockDim.x + threadIdx.x;
    long per = (long)Kp * dstLd;
    if (idx >= per * nBatch) return;
    int b = (int)(idx / per);
    long r = idx % per;
    int kp = (int)(r / dstLd), n = (int)(r % dstLd);
    float v0 = 0.f, v1 = 0.f;
    if (n < N) {
        const float* s = src + (long)b * srcBOff;
        v0 = s[(long)(2 * kp) * kStr + (long)n * nStr];
        v1 = s[(long)(2 * kp + 1) * kStr + (long)n * nStr];
    }
    uint32_t lo, hi = pack_hi(v0, v1, lo);
    dh[(long)b * dstBOff + r] = hi;
    dl[(long)b * dstBOff + r] = lo;
}

// A-format split (k contiguous): dst[m][kp]
__global__ void splitA_k(const float* __restrict__ src, uint32_t* __restrict__ dh,
                         uint32_t* __restrict__ dl, int M, int Kp, int lda)
{
    long idx = (long)blockIdx.x * blockDim.x + threadIdx.x;
    if (idx >= (long)M * Kp) return;
    int m = (int)(idx / Kp), kp = (int)(idx % Kp);
    float v0 = src[(long)m * lda + 2 * kp];
    float v1 = src[(long)m * lda + 2 * kp + 1];
    uint32_t lo, hi = pack_hi(v0, v1, lo);
    dh[idx] = hi; dl[idx] = lo;
}

// rkT split: dst[nh][dp] = pack(rk[2dp][nh], rk[2dp+1][nh])  (rk: [1024][16*64])
__global__ void rkTsplit_k(const float* __restrict__ rk, uint32_t* __restrict__ dh,
                           uint32_t* __restrict__ dl)
{
    int idx = blockIdx.x * blockDim.x + threadIdx.x;
    if (idx >= 1024 * 512) return;
    int nh = idx / 512, dp = idx % 512;
    float v0 = rk[(long)(2 * dp) * 1024 + nh];
    float v1 = rk[(long)(2 * dp + 1) * 1024 + nh];
    uint32_t lo, hi = pack_hi(v0, v1, lo);
    dh[idx] = hi; dl[idx] = lo;
}

// ---------------- relative-position basis ----------------
__global__ void relmat_k(float* __restrict__ R, int nU, int g, int d0)
{
    long idx = (long)blockIdx.x * blockDim.x + threadIdx.x;
    if (idx >= (long)nU * DMODEL) return;
    int u = (int)(idx / DMODEL), d = (int)(idx % DMODEL);
    int f = (d < 512) ? d : d - 512;
    float invf = expf(-(float)f * (9.210340371976184f / 512.0f));
    float arg = (float)(g * u + d0) * invf;
    R[idx] = (d < 512) ? sinf(arg) : cosf(arg);
}

// qw/qq bias-add, split output
__global__ void addbias2s_k(const float* __restrict__ q, const float* __restrict__ rw,
                            const float* __restrict__ rr,
                            uint32_t* __restrict__ qwh, uint32_t* __restrict__ qwl,
                            uint32_t* __restrict__ qqh, uint32_t* __restrict__ qql,
                            long total)
{
    long idx = (long)blockIdx.x * blockDim.x + threadIdx.x;
    if (idx >= total) return;
    long row = idx / 512;
    int d2 = (int)(idx % 512);
    float q0 = q[row * 1024 + 2 * d2], q1 = q[row * 1024 + 2 * d2 + 1];
    uint32_t lo, hi;
    hi = pack_hi(q0 + QSCALE * rw[2 * d2], q1 + QSCALE * rw[2 * d2 + 1], lo);
    qwh[idx] = hi; qwl[idx] = lo;
    hi = pack_hi(q0 + QSCALE * rr[2 * d2], q1 + QSCALE * rr[2 * d2 + 1], lo);
    qqh[idx] = hi; qql[idx] = lo;
}

// token-type biases
__global__ void ttb_k(const float* __restrict__ q, const float* __restrict__ rs,
                      const float* __restrict__ seg, float* __restrict__ tt0,
                      float* __restrict__ dtt, int Lq)
{
    int idx = blockIdx.x * blockDim.x + threadIdx.x;
    if (idx >= BATCH * NHEADS * Lq) return;
    int i = idx % Lq; int bn = idx / Lq; int n = bn % NHEADS; int b = bn / NHEADS;
    const float* qp  = q + ((long)(b * Lq + i)) * DMODEL + n * DHEAD;
    const float* rsp = rs + n * DHEAD;
    const float* s0  = seg + n * DHEAD;
    const float* s1  = seg + DMODEL + n * DHEAD;
    float t0 = 0.f, t1 = 0.f;
    #pragma unroll 8
    for (int h = 0; h < DHEAD; h++) {
        float v = qp[h] + QSCALE * rsp[h];
        t0 += v * s0[h];
        t1 += v * s1[h];
    }
    tt0[(long)bn * Lq + i] = t0;
    dtt[(long)bn * Lq + i] = t1 - t0;
}

// assemble scores + softmax; write split probs
__global__ void softmax_k(const float* __restrict__ S, const float* __restrict__ P,
                          uint32_t* __restrict__ Sh, uint32_t* __restrict__ Sl,
                          const float* __restrict__ tt0, const float* __restrict__ dtt,
                          const int* __restrict__ ids,
                          int Lq, int Lk, int nU, int cq, int ck, int u0, int pq, int pk)
{
    int i = blockIdx.x, n = blockIdx.y, b = blockIdx.z;
    int bn = b * NHEADS + n;
    const float* Srow = S + ((long)bn * Lq + i) * Lk;
    const float* Prow = P + ((long)bn * Lq + i) * nU;
    float t0 = tt0[(long)bn * Lq + i], dt = dtt[(long)bn * Lq + i];
    const int* idk = ids + b * 1024;
    int idq = idk[pq * i];
    int ubase = cq * i + u0;

    __shared__ float sh[MAXTOK];
    __shared__ float red[32];
    int tid = threadIdx.x;

    float lmax = -1e30f;
    for (int j = tid; j < Lk; j += blockDim.x) {
        float tok = (idk[pk * j] == idq) ? (t0 + dt) : t0;
        float v = Srow[j] + Prow[ubase + ck * j] + tok;
        sh[j] = v;
        lmax = fmaxf(lmax, v);
    }
    float bmax = blockReduceMax(lmax, red);

    float lsum = 0.f;
    for (int j = tid; j < Lk; j += blockDim.x) {
        float e = expf(sh[j] - bmax);
        sh[j] = e;
        lsum += e;
    }
    float bsum = blockReduceSum(lsum, red);
    float inv = 1.0f / bsum;

    long srow = ((long)bn * Lq + i) * (Lk >> 1);
    for (int j2 = tid; j2 < (Lk >> 1); j2 += blockDim.x) {
        uint32_t lo, hi = pack_hi(sh[2 * j2] * inv, sh[2 * j2 + 1] * inv, lo);
        Sh[srow + j2] = hi;
        Sl[srow + j2] = lo;
    }
}

// residual + LayerNorm; writes float out + split out
__global__ void ln_k(const float* __restrict__ qin, const float* __restrict__ tmp,
                     const float* __restrict__ gvec, const float* __restrict__ bvec,
                     float* __restrict__ out, uint32_t* __restrict__ oh,
                     uint32_t* __restrict__ ol)
{
    int r = blockIdx.x, tid = threadIdx.x;
    const float* x1 = qin + (long)r * DMODEL;
    const float* x2 = tmp + (long)r * DMODEL;
    __shared__ float red[32];
    float s = 0.f;
    for (int d = tid; d < DMODEL; d += blockDim.x) s += x1[d] + x2[d];
    float mu = blockReduceSum(s, red) * (1.0f / DMODEL);
    float vs = 0.f;
    for (int d = tid; d < DMODEL; d += blockDim.x) {
        float z = x1[d] + x2[d] - mu;
        vs += z * z;
    }
    float var = blockReduceSum(vs, red) * (1.0f / DMODEL);
    float rstd = rsqrtf(var + LNEPS);
    for (int d2 = tid; d2 < 512; d2 += blockDim.x) {
        int d0 = 2 * d2, d1 = d0 + 1;
        float o0 = (x1[d0] + x2[d0] - mu) * rstd * gvec[d0] + bvec[d0];
        float o1 = (x1[d1] + x2[d1] - mu) * rstd * gvec[d1] + bvec[d1];
        out[(long)r * DMODEL + d0] = o0;
        out[(long)r * DMODEL + d1] = o1;
        uint32_t lo, hi = pack_hi(o0, o1, lo);
        oh[(long)r * 512 + d2] = hi;
        ol[(long)r * 512 + d2] = lo;
    }
}

// upsample; writes float out + split out
__global__ void upsample_k(const float* __restrict__ h, float* __restrict__ out,
                           uint32_t* __restrict__ oh, uint32_t* __restrict__ ol, int Lin)
{
    long idx = (long)blockIdx.x * blockDim.x + threadIdx.x;
    long total = (long)BATCH * Lin * 512;
    if (idx >= total) return;
    int d2 = (int)(idx % 512);
    long bt = idx / 512;
    int t = (int)(bt % Lin);
    int b = (int)(bt / Lin);
    int tp = (t == 0) ? Lin - 1 : t - 1;
    const float* cr = h + ((long)b * Lin + t) * DMODEL + 2 * d2;
    const float* pr = h + ((long)b * Lin + tp) * DMODEL + 2 * d2;
    float c0 = cr[0], c1 = cr[1];
    float i0 = 0.5f * (c0 + pr[0]), i1 = 0.5f * (c1 + pr[1]);
    long r = (long)b * (2 * Lin) + 2 * t;
    out[r * DMODEL + 2 * d2]     = c0;
    out[r * DMODEL + 2 * d2 + 1] = c1;
    out[(r + 1) * DMODEL + 2 * d2]     = i0;
    out[(r + 1) * DMODEL + 2 * d2 + 1] = i1;
    uint32_t lo, hi = pack_hi(c0, c1, lo);
    oh[r * 512 + d2] = hi; ol[r * 512 + d2] = lo;
    hi = pack_hi(i0, i1, lo);
    oh[(r + 1) * 512 + d2] = hi; ol[(r + 1) * 512 + d2] = lo;
}

// ---------------- host ----------------
static void gemmS(const uint32_t* Ah, const uint32_t* Al,
                  const uint32_t* Bh, const uint32_t* Bl,
                  const float* bias, float* C, uint32_t* Ch, uint32_t* Cl,
                  int M, int N, int Kp, int ldau, int ldbu, int ldc, int ldcs,
                  long aO, long aI, long bO, long bI, long cO, long cI,
                  int innerCount, int batches, float alpha, float biasAlpha,
                  int posWin = 0, int pcq = 0, int pck = 0, int pu0 = 0, int pLk = 0)
{
    dim3 grid((N + 127) / 128, (M + 127) / 128, batches);
    gemm_tcs<<<grid, 256>>>(Ah, Al, Bh, Bl, bias, C, Ch, Cl,
                            M, N, Kp, ldau, ldbu, ldc, ldcs,
                            aO, aI, bO, bI, cO, cI, innerCount, alpha, biasAlpha,
                            posWin, pcq, pck, pu0, pLk);
}

#define GS(sym, var) cudaGetSymbolAddress((void**)&var, sym)

extern "C" void kernel_launch(void* const* d_in, const int* in_sizes, int n_in,
                              void* d_out, int out_size)
{
    const float* final_hidden = (const float*)d_in[0];
    const int*   tok_ids      = (const int*)d_in[5];
    const float* Wq = (const float*)d_in[6];
    const float* bq = (const float*)d_in[7];
    const float* Wk = (const float*)d_in[8];
    const float* bk = (const float*)d_in[9];
    const float* Wv = (const float*)d_in[10];
    const float* bv = (const float*)d_in[11];
    const float* rw = (const float*)d_in[12];
    const float* rr = (const float*)d_in[13];
    const float* rs = (const float*)d_in[14];
    const float* rk = (const float*)d_in[15];
    const float* sg = (const float*)d_in[16];
    const float* Wp = (const float*)d_in[17];
    const float* bp = (const float*)d_in[18];
    const float* lg = (const float*)d_in[19];
    const float* lb = (const float*)d_in[20];
    float* out = (float*)d_out;

    float *p_q,*p_k,*p_v,*p_tmp,*p_hA,*p_hB,*p_up,*p_S,*p_P,*p_REL,*p_R1,*p_R2,*p_R3,*p_t0,*p_dt;
    GS(g_q,p_q); GS(g_k,p_k); GS(g_v,p_v); GS(g_tmp,p_tmp);
    GS(g_hA,p_hA); GS(g_hB,p_hB); GS(g_up,p_up);
    GS(g_S,p_S); GS(g_P,p_P); GS(g_REL,p_REL);
    GS(g_R1,p_R1); GS(g_R2,p_R2); GS(g_R3,p_R3);
    GS(g_tt0,p_t0); GS(g_dtt,p_dt);

    uint32_t *wqh,*wql,*wkh,*wkl,*wvh,*wvl,*wph,*wpl;
    uint32_t *r1h,*r1l,*r2h,*r2l,*r3h,*r3l,*rkth,*rktl,*relh,*rell;
    uint32_t *ksh,*ksl,*vsh,*vsl,*qwh,*qwl,*qqh,*qql,*ssh,*ssl,*vch,*vcl,*hsh,*hsl,*ush,*usl;
    GS(g_Wqh,wqh); GS(g_Wql,wql); GS(g_Wkh,wkh); GS(g_Wkl,wkl);
    GS(g_Wvh,wvh); GS(g_Wvl,wvl); GS(g_Wph,wph); GS(g_Wpl,wpl);
    GS(g_R1h,r1h); GS(g_R1l,r1l); GS(g_R2h,r2h); GS(g_R2l,r2l); GS(g_R3h,r3h); GS(g_R3l,r3l);
    GS(g_rkTh,rkth); GS(g_rkTl,rktl); GS(g_RELh,relh); GS(g_RELl,rell);
    GS(g_ksh,ksh); GS(g_ksl,ksl); GS(g_vsh,vsh); GS(g_vsl,vsl);
    GS(g_qwh,qwh); GS(g_qwl,qwl); GS(g_qqh,qqh); GS(g_qql,qql);
    GS(g_Ssh,ssh); GS(g_Ssl,ssl); GS(g_vch,vch); GS(g_vcl,vcl);
    GS(g_hsh,hsh); GS(g_hsl,hsl); GS(g_ush,ush); GS(g_usl,usl);

    // ---- setup: rel-pos bases + one-time splits ----
    relmat_k<<<(unsigned)(((long)NU1*DMODEL + 255)/256), 256>>>(p_R1, NU1, 1, -1023);
    relmat_k<<<(unsigned)(((long)NU2*DMODEL + 255)/256), 256>>>(p_R2, NU2, 2, -1022);
    relmat_k<<<(unsigned)(((long)NU3*DMODEL + 255)/256), 256>>>(p_R3, NU3, 4, -1020);
    {
        long t;
        t = (long)512*NUP1; splitB_k<<<(unsigned)((t+255)/256),256>>>(p_R1, r1h, r1l, 512, NU1, NUP1, 1, DMODEL, 0, 0, 1);
        t = (long)512*1024; splitB_k<<<(unsigned)((t+255)/256),256>>>(p_R2, r2h, r2l, 512, NU2, 1024, 1, DMODEL, 0, 0, 1);
        t = (long)512*512;  splitB_k<<<(unsigned)((t+255)/256),256>>>(p_R3, r3h, r3l, 512, NU3, 512,  1, DMODEL, 0, 0, 1);
        t = (long)6144*1024;
        splitB_k<<<(unsigned)((t+255)/256),256>>>(Wq, wqh, wql, 6144, 1024, 1024, 1024, 1, 0, 0, 1);
        splitB_k<<<(unsigned)((t+255)/256),256>>>(Wk, wkh, wkl, 6144, 1024, 1024, 1024, 1, 0, 0, 1);
        splitB_k<<<(unsigned)((t+255)/256),256>>>(Wv, wvh, wvl, 6144, 1024, 1024, 1024, 1, 0, 0, 1);
        splitB_k<<<(unsigned)((t+255)/256),256>>>(Wp, wph, wpl, 6144, 1024, 1024, 1024, 1, 0, 0, 1);
        t = (long)512*512;  splitA_k<<<(unsigned)((t+255)/256),256>>>(final_hidden, hsh, hsl, 512, 512, 1024);
    }

    const float* hidden = final_hidden;
    float* bufs[2] = {p_hA, p_hB};
    int pb = 0;

    for (int l = 11; l >= 0; --l) {
        int Lq, Lk, do_up, nU, nUp, cq, ck, u0, pq, pk;
        uint32_t *Rh, *Rl;
        if (l <= 3)      { Lq=1024; Lk=1024; do_up=0; nU=NU1; nUp=NUP1; Rh=r1h; Rl=r1l; cq= 1; ck=-1; u0=1023; pq=1; pk=1; }
        else if (l == 4) { Lq=1024; Lk=512;  do_up=1; nU=NU1; nUp=NUP1; Rh=r1h; Rl=r1l; cq=-1; ck= 2; u0=1023; pq=1; pk=2; }
        else if (l <= 7) { Lq=512;  Lk=512;  do_up=0; nU=NU2; nUp=1024; Rh=r2h; Rl=r2l; cq= 1; ck=-1; u0=511;  pq=2; pk=2; }
        else if (l == 8) { Lq=512;  Lk=256;  do_up=1; nU=NU2; nUp=1024; Rh=r2h; Rl=r2l; cq=-1; ck= 2; u0=511;  pq=2; pk=4; }
        else             { Lq=256;  Lk=256;  do_up=0; nU=NU3; nUp=512;  Rh=r3h; Rl=r3l; cq= 1; ck=-1; u0=255;  pq=4; pk=4; }

        if (l == 11) { long t = (long)BATCH*256*512; upsample_k<<<(unsigned)((t+255)/256),256>>>(hidden, p_up, ush, usl, 256); }
        if (l == 7)  { long t = (long)BATCH*512*512; upsample_k<<<(unsigned)((t+255)/256),256>>>(hidden, p_up, ush, usl, 512); }

        const float* q_in_f = do_up ? p_up : hidden;
        uint32_t* qinh = do_up ? ush : hsh;
        uint32_t* qinl = do_up ? usl : hsl;

        // rkT split + REL = rkT @ R^T  (per head)
        rkTsplit_k<<<(1024*512 + 255)/256, 256>>>(rk + (long)l*DMODEL*DMODEL, rkth, rktl);
        gemmS(rkth, rktl, Rh, Rl, nullptr, p_REL, nullptr, nullptr,
              64, nU, 512, 512, nUp, nU, 0,
              0, (long)64*512, 0, 0, 0, (long)64*nU,
              16, 16, 1.f, 0.f);
        // REL split (rows = h pairs)
        {
            long t = (long)16*32*nUp;
            splitB_k<<<(unsigned)((t+255)/256),256>>>(p_REL, relh, rell, 32, nU, nUp,
                                                      nU, 1, (long)64*nU, (long)32*nUp, 16);
        }

        // Q/K/V projections
        gemmS(qinh, qinl, wqh + (long)l*512*1024, wql + (long)l*512*1024, bq + l*DMODEL,
              p_q, nullptr, nullptr,
              BATCH*Lq, DMODEL, 512, 512, 1024, DMODEL, 0,
              0,0,0,0,0,0, 1, 1, QSCALE, QSCALE);
        gemmS(hsh, hsl, wkh + (long)l*512*1024, wkl + (long)l*512*1024, bk + l*DMODEL,
              p_k, nullptr, nullptr,
              BATCH*Lk, DMODEL, 512, 512, 1024, DMODEL, 0,
              0,0,0,0,0,0, 1, 1, 1.f, 1.f);
        gemmS(hsh, hsl, wvh + (long)l*512*1024, wvl + (long)l*512*1024, bv + l*DMODEL,
              p_v, nullptr, nullptr,
              BATCH*Lk, DMODEL, 512, 512, 1024, DMODEL, 0,
              0,0,0,0,0,0, 1, 1, 1.f, 1.f);

        // k split (k-dim = d within head, pairs along d): dst[b][dp][j]
        {
            long t = (long)2*512*Lk;
            splitB_k<<<(unsigned)((t+255)/256),256>>>(p_k, ksh, ksl, 512, Lk, Lk,
                                                      1, DMODEL, (long)Lk*DMODEL, (long)512*Lk, 2);
        }
        // v split (k-dim = token j, pairs along j): dst[b][jp][d]
        {
            long t = (long)2*(Lk/2)*DMODEL;
            splitB_k<<<(unsigned)((t+255)/256),256>>>(p_v, vsh, vsl, Lk/2, DMODEL, DMODEL,
                                                      DMODEL, 1, (long)Lk*DMODEL, (long)(Lk/2)*DMODEL, 2);
        }
        // qw/qq splits
        {
            long t = (long)BATCH*Lq*512;
            addbias2s_k<<<(unsigned)((t+255)/256),256>>>(p_q, rw + l*DMODEL, rr + l*DMODEL,
                                                         qwh, qwl, qqh, qql, t);
        }
        // token-type biases
        {
            int t = BATCH*NHEADS*Lq;
            ttb_k<<<(t+255)/256, 256>>>(p_q, rs + l*DMODEL, sg + (long)l*2*DMODEL, p_t0, p_dt, Lq);
        }

        // content scores
        gemmS(qwh, qwl, ksh, ksl, nullptr, p_S, nullptr, nullptr,
              Lq, Lk, 32, 512, Lk, Lk, 0,
              (long)Lq*512, 32, (long)512*Lk, (long)32*Lk,
              (long)NHEADS*Lq*Lk, (long)Lq*Lk,
              NHEADS, BATCH*NHEADS, 1.f, 0.f);

        // P (rel-pos projections), window-culled
        gemmS(qqh, qql, relh, rell, nullptr, p_P, nullptr, nullptr,
              Lq, nU, 32, 512, nUp, nU, 0,
              (long)Lq*512, 32, 0, (long)32*nUp,
              (long)NHEADS*Lq*nU, (long)Lq*nU,
              NHEADS, BATCH*NHEADS, 1.f, 0.f,
              1, cq, ck, u0, Lk);

        // softmax (writes split probs)
        {
            dim3 grid(Lq, NHEADS, BATCH);
            softmax_k<<<grid, 256>>>(p_S, p_P, ssh, ssl, p_t0, p_dt, tok_ids,
                                     Lq, Lk, nU, cq, ck, u0, pq, pk);
        }

        // vec = prob @ v (split output)
        gemmS(ssh, ssl, vsh, vsl, nullptr, nullptr, vch, vcl,
              Lq, DHEAD, Lk/2, Lk/2, DMODEL, 0, 512,
              (long)NHEADS*Lq*(Lk/2), (long)Lq*(Lk/2),
              (long)(Lk/2)*DMODEL, 64,
              (long)Lq*512, 32,
              NHEADS, BATCH*NHEADS, 1.f, 0.f);

        // post projection
        gemmS(vch, vcl, wph + (long)l*512*1024, wpl + (long)l*512*1024, bp + l*DMODEL,
              p_tmp, nullptr, nullptr,
              BATCH*Lq, DMODEL, 512, 512, 1024, DMODEL, 0,
              0,0,0,0,0,0, 1, 1, 1.f, 1.f);

        // residual + LayerNorm (writes float hidden + split hidden)
        float* dst = (l == 0) ? out : bufs[pb];
        ln_k<<<BATCH*Lq, 256>>>(q_in_f, p_tmp, lg + l*DMODEL, lb + l*DMODEL, dst, hsh, hsl);

        hidden = dst;
        pb ^= 1;
    }
}